// round 2
// baseline (speedup 1.0000x reference)
#include <cuda_runtime.h>
#include <math.h>

#define BB 2
#define TT 2048
#define DD 1024
#define NH 16
#define DH 64
#define BT (BB*TT)

// Scratch (allocation-free rule: __device__ globals)
__device__ float g_Q[BB*NH*TT*DH];   // [b,h,t,d]
__device__ float g_K[BB*NH*TT*DH];
__device__ float g_V[BB*NH*TT*DH];
__device__ float g_A[BT*DD];         // [b,t,h*dh]  (attention output, pre out-proj)

// ---------------------------------------------------------------------------
// SGEMM NT: C[M,N] = A[M,K] * W[N,K]^T     (both row-major, K contiguous)
// MODE 0: C row-major [M,N]
// MODE 1: scatter C[r,c] into head layout [b,h,t,d]
// BM=BN=128, BK=8, 256 threads, 8x8 microtile
// ---------------------------------------------------------------------------
template<int MODE>
__global__ __launch_bounds__(256)
void sgemm_nt(const float* __restrict__ A, const float* __restrict__ W,
              float* __restrict__ C, int M, int N, int K)
{
    __shared__ float As[8][128];
    __shared__ float Bs[8][128];
    const int tid = threadIdx.x;
    const int tx = tid & 15;          // 0..15  (N dir)
    const int ty = tid >> 4;          // 0..15  (M dir)
    const int rowBase = blockIdx.y * 128;
    const int colBase = blockIdx.x * 128;

    float acc[8][8];
#pragma unroll
    for (int i = 0; i < 8; ++i)
#pragma unroll
        for (int j = 0; j < 8; ++j) acc[i][j] = 0.f;

    const int lr = tid >> 1;              // 0..127 row within tile
    const int lk = (tid & 1) << 2;        // 0 or 4
    const float* Ap = A + (size_t)(rowBase + lr) * K + lk;
    const float* Wp = W + (size_t)(colBase + lr) * K + lk;

    for (int k0 = 0; k0 < K; k0 += 8) {
        float4 av = *(const float4*)(Ap + k0);
        float4 bv = *(const float4*)(Wp + k0);
        __syncthreads();
        As[lk+0][lr] = av.x; As[lk+1][lr] = av.y;
        As[lk+2][lr] = av.z; As[lk+3][lr] = av.w;
        Bs[lk+0][lr] = bv.x; Bs[lk+1][lr] = bv.y;
        Bs[lk+2][lr] = bv.z; Bs[lk+3][lr] = bv.w;
        __syncthreads();
#pragma unroll
        for (int kk = 0; kk < 8; ++kk) {
            float a[8], b[8];
            *(float4*)(a)   = *(const float4*)&As[kk][ty*8];
            *(float4*)(a+4) = *(const float4*)&As[kk][ty*8+4];
            *(float4*)(b)   = *(const float4*)&Bs[kk][tx*8];
            *(float4*)(b+4) = *(const float4*)&Bs[kk][tx*8+4];
#pragma unroll
            for (int i = 0; i < 8; ++i)
#pragma unroll
                for (int j = 0; j < 8; ++j)
                    acc[i][j] = fmaf(a[i], b[j], acc[i][j]);
        }
    }

#pragma unroll
    for (int i = 0; i < 8; ++i) {
        const int r = rowBase + ty*8 + i;
#pragma unroll
        for (int jb = 0; jb < 8; jb += 4) {
            const int c = colBase + tx*8 + jb;
            float4 v = make_float4(acc[i][jb], acc[i][jb+1], acc[i][jb+2], acc[i][jb+3]);
            if (MODE == 0) {
                *(float4*)&C[(size_t)r * N + c] = v;
            } else {
                const int b = r / TT, t = r % TT;
                const int h = c / DH, d = c % DH;
                *(float4*)&C[(((size_t)(b*NH + h))*TT + t)*DH + d] = v;
            }
        }
    }
}

// ---------------------------------------------------------------------------
// RoPE on interleaved pairs, applied in-place to Q and K ([b,h,t,d] layout)
// ---------------------------------------------------------------------------
__global__ void rope_kernel(float* __restrict__ Q, float* __restrict__ K)
{
    const int id = blockIdx.x * blockDim.x + threadIdx.x;   // [0, B*H*T*32)
    const int pair = id & 31;
    const int rest = id >> 5;
    const int t  = rest % TT;
    const int bh = rest / TT;
    const size_t base = ((size_t)bh * TT + t) * DH + 2*pair;

    const float freq = powf(10000.0f, -(float)pair * (1.0f/32.0f));
    const float ang = (float)t * freq;
    float s, c;
    sincosf(ang, &s, &c);

    float q0 = Q[base], q1 = Q[base+1];
    Q[base]   = c*q0 - s*q1;
    Q[base+1] = s*q0 + c*q1;
    float k0 = K[base], k1 = K[base+1];
    K[base]   = c*k0 - s*k1;
    K[base+1] = s*k0 + c*k1;
}

// ---------------------------------------------------------------------------
// Causal flash attention, fp32.  BM=128 q-rows, BN=64 k-cols, dh=64.
// 128 threads (16 row-groups x 8 col-groups), 8x8 microtile.
// Dynamic smem: Qs[d][128] 32KB | KP (Ks[d][64] then Ps[k][128]) 32KB | Vs[k][64] 16KB
// Output into g_A layout [b, t, h*dh].
// ---------------------------------------------------------------------------
__global__ __launch_bounds__(128)
void flash_attn(const float* __restrict__ Q, const float* __restrict__ K,
                const float* __restrict__ V, float* __restrict__ Ao)
{
    extern __shared__ float sm[];
    float* Qs = sm;                    // Qs[d*128 + r]
    float* KP = sm + 64*128;           // Ks[d*64 + c]  /  Ps[k*128 + r]
    float* Vs = sm + 64*128 + 64*128;  // Vs[k*64 + c]

    const int tid = threadIdx.x;
    const int tx = tid & 7;            // col group
    const int ty = tid >> 3;           // row group
    const int qtile = blockIdx.x;
    const int bh    = blockIdx.y;
    const int qbase = qtile * 128;
    const float* Qp = Q + (size_t)bh * TT * DH;
    const float* Kp = K + (size_t)bh * TT * DH;
    const float* Vp = V + (size_t)bh * TT * DH;

    // Load Q tile transposed: Qs[d][r]
#pragma unroll
    for (int p = 0; p < 16; ++p) {
        const int flat = (tid + p*128) * 4;
        const int r = flat >> 6, d = flat & 63;
        float4 v = *(const float4*)&Qp[(size_t)(qbase + r)*DH + d];
        Qs[(d+0)*128 + r] = v.x; Qs[(d+1)*128 + r] = v.y;
        Qs[(d+2)*128 + r] = v.z; Qs[(d+3)*128 + r] = v.w;
    }

    float m[8], l[8], o[8][8];
#pragma unroll
    for (int i = 0; i < 8; ++i) {
        m[i] = -1e30f; l[i] = 0.f;
#pragma unroll
        for (int j = 0; j < 8; ++j) o[i][j] = 0.f;
    }

    const int lastKt = 2*qtile + 1;
    for (int kt = 0; kt <= lastKt; ++kt) {
        const int kbase = kt * 64;
        __syncthreads();   // previous iteration done reading KP/Vs (also covers Q load)

        // Load K transposed (Ks[d][c]) and V natural (Vs[k][c])
#pragma unroll
        for (int p = 0; p < 8; ++p) {
            const int flat = (tid + p*128) * 4;
            const int r = flat >> 6, d = flat & 63;
            float4 kv = *(const float4*)&Kp[(size_t)(kbase + r)*DH + d];
            KP[(d+0)*64 + r] = kv.x; KP[(d+1)*64 + r] = kv.y;
            KP[(d+2)*64 + r] = kv.z; KP[(d+3)*64 + r] = kv.w;
            float4 vv = *(const float4*)&Vp[(size_t)(kbase + r)*DH + d];
            *(float4*)&Vs[r*64 + d] = vv;
        }
        __syncthreads();

        // S = Q K^T  (8x8 per thread)
        float s[8][8];
#pragma unroll
        for (int i = 0; i < 8; ++i)
#pragma unroll
            for (int j = 0; j < 8; ++j) s[i][j] = 0.f;

#pragma unroll 8
        for (int kk = 0; kk < 64; ++kk) {
            float a[8], b[8];
            *(float4*)(a)   = *(const float4*)&Qs[kk*128 + ty*8];
            *(float4*)(a+4) = *(const float4*)&Qs[kk*128 + ty*8 + 4];
            *(float4*)(b)   = *(const float4*)&KP[kk*64 + tx*8];
            *(float4*)(b+4) = *(const float4*)&KP[kk*64 + tx*8 + 4];
#pragma unroll
            for (int i = 0; i < 8; ++i)
#pragma unroll
                for (int j = 0; j < 8; ++j)
                    s[i][j] = fmaf(a[i], b[j], s[i][j]);
        }

        // scale + causal mask (mask only when tile straddles the diagonal)
        const float sc = 0.125f;    // 1/sqrt(64)
        if (kbase + 63 > qbase) {
#pragma unroll
            for (int i = 0; i < 8; ++i) {
                const int qi = qbase + ty*8 + i;
#pragma unroll
                for (int j = 0; j < 8; ++j) {
                    const int kj = kbase + tx*8 + j;
                    s[i][j] = (kj <= qi) ? s[i][j]*sc : -1e30f;
                }
            }
        } else {
#pragma unroll
            for (int i = 0; i < 8; ++i)
#pragma unroll
                for (int j = 0; j < 8; ++j) s[i][j] *= sc;
        }

        // Online softmax: reductions across the 8-lane col group via shfl
#pragma unroll
        for (int i = 0; i < 8; ++i) {
            float mx = s[i][0];
#pragma unroll
            for (int j = 1; j < 8; ++j) mx = fmaxf(mx, s[i][j]);
            mx = fmaxf(mx, __shfl_xor_sync(0xffffffffu, mx, 1));
            mx = fmaxf(mx, __shfl_xor_sync(0xffffffffu, mx, 2));
            mx = fmaxf(mx, __shfl_xor_sync(0xffffffffu, mx, 4));
            const float mn = fmaxf(m[i], mx);
            const float al = expf(m[i] - mn);
            m[i] = mn;
            float rs = 0.f;
#pragma unroll
            for (int j = 0; j < 8; ++j) { s[i][j] = expf(s[i][j] - mn); rs += s[i][j]; }
            rs += __shfl_xor_sync(0xffffffffu, rs, 1);
            rs += __shfl_xor_sync(0xffffffffu, rs, 2);
            rs += __shfl_xor_sync(0xffffffffu, rs, 4);
            l[i] = l[i]*al + rs;
#pragma unroll
            for (int j = 0; j < 8; ++j) o[i][j] *= al;
        }

        __syncthreads();   // everyone done reading KP as Ks
        // Store P transposed: Ps[k][r]
#pragma unroll
        for (int j = 0; j < 8; ++j) {
            float4 p0 = make_float4(s[0][j], s[1][j], s[2][j], s[3][j]);
            float4 p1 = make_float4(s[4][j], s[5][j], s[6][j], s[7][j]);
            *(float4*)&KP[(tx*8+j)*128 + ty*8]     = p0;
            *(float4*)&KP[(tx*8+j)*128 + ty*8 + 4] = p1;
        }
        __syncthreads();

        // O += P V
#pragma unroll 8
        for (int kk = 0; kk < 64; ++kk) {
            float a[8], b[8];
            *(float4*)(a)   = *(const float4*)&KP[kk*128 + ty*8];
            *(float4*)(a+4) = *(const float4*)&KP[kk*128 + ty*8 + 4];
            *(float4*)(b)   = *(const float4*)&Vs[kk*64 + tx*8];
            *(float4*)(b+4) = *(const float4*)&Vs[kk*64 + tx*8 + 4];
#pragma unroll
            for (int i = 0; i < 8; ++i)
#pragma unroll
                for (int j = 0; j < 8; ++j)
                    o[i][j] = fmaf(a[i], b[j], o[i][j]);
        }
    }

    // Epilogue: normalize and write to [b, t, h*dh]
    const int b = bh / NH, hh = bh % NH;
#pragma unroll
    for (int i = 0; i < 8; ++i) {
        const float inv = 1.f / l[i];
        const int t = qbase + ty*8 + i;
        float* dst = &Ao[((size_t)(b*TT + t))*DD + hh*DH + tx*8];
        float4 v0 = make_float4(o[i][0]*inv, o[i][1]*inv, o[i][2]*inv, o[i][3]*inv);
        float4 v1 = make_float4(o[i][4]*inv, o[i][5]*inv, o[i][6]*inv, o[i][7]*inv);
        *(float4*)(dst)     = v0;
        *(float4*)(dst + 4) = v1;
    }
}

// ---------------------------------------------------------------------------
extern "C" void kernel_launch(void* const* d_in, const int* in_sizes, int n_in,
                              void* d_out, int out_size)
{
    const float* h  = (const float*)d_in[0];
    const float* wq = (const float*)d_in[1];
    const float* wk = (const float*)d_in[2];
    const float* wv = (const float*)d_in[3];
    const float* wo = (const float*)d_in[4];
    float* out = (float*)d_out;
    (void)in_sizes; (void)n_in; (void)out_size;

    float *pQ, *pK, *pV, *pA;
    cudaGetSymbolAddress((void**)&pQ, g_Q);
    cudaGetSymbolAddress((void**)&pK, g_K);
    cudaGetSymbolAddress((void**)&pV, g_V);
    cudaGetSymbolAddress((void**)&pA, g_A);

    cudaFuncSetAttribute(flash_attn, cudaFuncAttributeMaxDynamicSharedMemorySize, 81920);

    const dim3 ggrid(DD/128, BT/128);   // (8, 32)
    sgemm_nt<1><<<ggrid, 256>>>(h, wq, pQ, BT, DD, DD);
    sgemm_nt<1><<<ggrid, 256>>>(h, wk, pK, BT, DD, DD);
    sgemm_nt<1><<<ggrid, 256>>>(h, wv, pV, BT, DD, DD);

    const int nrope = BB*NH*TT*(DH/2);          // 2,097,152
    rope_kernel<<<nrope/256, 256>>>(pQ, pK);

    flash_attn<<<dim3(TT/128, BB*NH), 128, 81920>>>(pQ, pK, pV, pA);

    sgemm_nt<0><<<ggrid, 256>>>(pA, wo, out, BT, DD, DD);
}

// round 3
// speedup vs baseline: 1.5803x; 1.5803x over previous
#include <cuda_runtime.h>
#include <math.h>

#define BB 2
#define TT 2048
#define DD 1024
#define NH 16
#define DH 64
#define BT (BB*TT)

// Scratch (allocation-free rule: __device__ globals)
__device__ float g_Q[BB*NH*TT*DH];   // [b,h,t,d]
__device__ float g_K[BB*NH*TT*DH];
__device__ float g_V[BB*NH*TT*DH];
__device__ float g_A[BT*DD];         // [b,t,h*dh]  (attention output, pre out-proj)

__device__ __forceinline__ unsigned f2tf32(float x) {
    unsigned r;
    asm("cvt.rna.tf32.f32 %0, %1;" : "=r"(r) : "f"(x));
    return r;
}

#define MMA_TF32(d0,d1,d2,d3,a0,a1,a2,a3,b0,b1)                                   \
    asm volatile("mma.sync.aligned.m16n8k8.row.col.f32.tf32.tf32.f32 "            \
                 "{%0,%1,%2,%3},{%4,%5,%6,%7},{%8,%9},{%0,%1,%2,%3};"             \
                 : "+f"(d0), "+f"(d1), "+f"(d2), "+f"(d3)                         \
                 : "r"(a0), "r"(a1), "r"(a2), "r"(a3), "r"(b0), "r"(b1))

// ---------------------------------------------------------------------------
// tf32 tensor-core GEMM NT: C[M,N] = A[M,K] * W[N,K]^T  (row-major, K contig)
// MODE 0: C row-major [M,N];  MODE 1: scatter into head layout [b,h,t,d]
// Block tile 128x128, BK=16, 256 threads = 8 warps (2x4), warp tile 64x32.
// Smem stride 136 words -> fragment gathers are bank-conflict-free:
//   bank(k,m) = (8k + m) mod 32, k in 0..3 (x8 -> {0,8,16,24}), m in 0..7.
// ---------------------------------------------------------------------------
template<int MODE>
__global__ __launch_bounds__(256)
void tgemm_nt(const float* __restrict__ A, const float* __restrict__ W,
              float* __restrict__ C, int M, int N, int K)
{
    __shared__ unsigned As[16][136];
    __shared__ unsigned Bs[16][136];

    const int tid = threadIdx.x;
    const int lane = tid & 31;
    const int warp = tid >> 5;
    const int grp = lane >> 2;      // 0..7
    const int qk  = lane & 3;       // 0..3
    const int warpM = (warp & 1) * 64;
    const int warpN = (warp >> 1) * 32;
    const int rowBase = blockIdx.y * 128;
    const int colBase = blockIdx.x * 128;

    float acc[4][4][4];
#pragma unroll
    for (int mt = 0; mt < 4; ++mt)
#pragma unroll
        for (int nt = 0; nt < 4; ++nt)
#pragma unroll
            for (int r = 0; r < 4; ++r) acc[mt][nt][r] = 0.f;

    const int lr = tid >> 1;              // 0..127
    const int lk = (tid & 1) << 2;        // 0 or 4
    const float* Ap = A + (size_t)(rowBase + lr) * K + lk;
    const float* Wp = W + (size_t)(colBase + lr) * K + lk;

    for (int k0 = 0; k0 < K; k0 += 16) {
        float4 a0v = *(const float4*)(Ap + k0);
        float4 a1v = *(const float4*)(Ap + k0 + 8);
        float4 b0v = *(const float4*)(Wp + k0);
        float4 b1v = *(const float4*)(Wp + k0 + 8);
        __syncthreads();
        As[lk+0][lr] = f2tf32(a0v.x); As[lk+1][lr] = f2tf32(a0v.y);
        As[lk+2][lr] = f2tf32(a0v.z); As[lk+3][lr] = f2tf32(a0v.w);
        As[lk+8][lr] = f2tf32(a1v.x); As[lk+9][lr] = f2tf32(a1v.y);
        As[lk+10][lr]= f2tf32(a1v.z); As[lk+11][lr]= f2tf32(a1v.w);
        Bs[lk+0][lr] = f2tf32(b0v.x); Bs[lk+1][lr] = f2tf32(b0v.y);
        Bs[lk+2][lr] = f2tf32(b0v.z); Bs[lk+3][lr] = f2tf32(b0v.w);
        Bs[lk+8][lr] = f2tf32(b1v.x); Bs[lk+9][lr] = f2tf32(b1v.y);
        Bs[lk+10][lr]= f2tf32(b1v.z); Bs[lk+11][lr]= f2tf32(b1v.w);
        __syncthreads();

#pragma unroll
        for (int ks = 0; ks < 2; ++ks) {
            const int kb = ks * 8;
            unsigned af[4][4], bf[4][2];
#pragma unroll
            for (int mt = 0; mt < 4; ++mt) {
                const int m0 = warpM + mt*16 + grp;
                af[mt][0] = As[kb + qk    ][m0];
                af[mt][1] = As[kb + qk    ][m0 + 8];
                af[mt][2] = As[kb + 4 + qk][m0];
                af[mt][3] = As[kb + 4 + qk][m0 + 8];
            }
#pragma unroll
            for (int nt = 0; nt < 4; ++nt) {
                const int n0 = warpN + nt*8 + grp;
                bf[nt][0] = Bs[kb + qk    ][n0];
                bf[nt][1] = Bs[kb + 4 + qk][n0];
            }
#pragma unroll
            for (int mt = 0; mt < 4; ++mt)
#pragma unroll
                for (int nt = 0; nt < 4; ++nt)
                    MMA_TF32(acc[mt][nt][0], acc[mt][nt][1],
                             acc[mt][nt][2], acc[mt][nt][3],
                             af[mt][0], af[mt][1], af[mt][2], af[mt][3],
                             bf[nt][0], bf[nt][1]);
        }
    }

    // Epilogue: c0/c1 at (row, col..col+1); c2/c3 at row+8.
#pragma unroll
    for (int mt = 0; mt < 4; ++mt) {
#pragma unroll
        for (int nt = 0; nt < 4; ++nt) {
            const int r0 = rowBase + warpM + mt*16 + grp;
            const int c  = colBase + warpN + nt*8 + 2*qk;
            float2 v0 = make_float2(acc[mt][nt][0], acc[mt][nt][1]);
            float2 v1 = make_float2(acc[mt][nt][2], acc[mt][nt][3]);
            if (MODE == 0) {
                *(float2*)&C[(size_t)r0 * N + c]     = v0;
                *(float2*)&C[(size_t)(r0+8) * N + c] = v1;
            } else {
                const int h = c / DH, d = c % DH;
                const int b0 = r0 / TT, t0 = r0 % TT;
                const int b1 = (r0+8) / TT, t1 = (r0+8) % TT;
                *(float2*)&C[(((size_t)(b0*NH + h))*TT + t0)*DH + d] = v0;
                *(float2*)&C[(((size_t)(b1*NH + h))*TT + t1)*DH + d] = v1;
            }
        }
    }
}

// ---------------------------------------------------------------------------
// RoPE on interleaved pairs, applied in-place to Q and K ([b,h,t,d] layout)
// ---------------------------------------------------------------------------
__global__ void rope_kernel(float* __restrict__ Q, float* __restrict__ K)
{
    const int id = blockIdx.x * blockDim.x + threadIdx.x;   // [0, B*H*T*32)
    const int pair = id & 31;
    const int rest = id >> 5;
    const int t  = rest % TT;
    const int bh = rest / TT;
    const size_t base = ((size_t)bh * TT + t) * DH + 2*pair;

    const float freq = powf(10000.0f, -(float)pair * (1.0f/32.0f));
    const float ang = (float)t * freq;
    float s, c;
    sincosf(ang, &s, &c);

    float q0 = Q[base], q1 = Q[base+1];
    Q[base]   = c*q0 - s*q1;
    Q[base+1] = s*q0 + c*q1;
    float k0 = K[base], k1 = K[base+1];
    K[base]   = c*k0 - s*k1;
    K[base+1] = s*k0 + c*k1;
}

// ---------------------------------------------------------------------------
// Causal flash attention, fp32.  BM=128 q-rows, BN=64 k-cols, dh=64.
// 128 threads (16 row-groups x 8 col-groups), 8x8 microtile.
// Dynamic smem: Qs[d][128] 32KB | KP (Ks[d][64] then Ps[k][128]) 32KB | Vs 16KB
// ---------------------------------------------------------------------------
__global__ __launch_bounds__(128)
void flash_attn(const float* __restrict__ Q, const float* __restrict__ K,
                const float* __restrict__ V, float* __restrict__ Ao)
{
    extern __shared__ float sm[];
    float* Qs = sm;                    // Qs[d*128 + r]
    float* KP = sm + 64*128;           // Ks[d*64 + c]  /  Ps[k*128 + r]
    float* Vs = sm + 64*128 + 64*128;  // Vs[k*64 + c]

    const int tid = threadIdx.x;
    const int tx = tid & 7;
    const int ty = tid >> 3;
    const int qtile = blockIdx.x;
    const int bh    = blockIdx.y;
    const int qbase = qtile * 128;
    const float* Qp = Q + (size_t)bh * TT * DH;
    const float* Kp = K + (size_t)bh * TT * DH;
    const float* Vp = V + (size_t)bh * TT * DH;

#pragma unroll
    for (int p = 0; p < 16; ++p) {
        const int flat = (tid + p*128) * 4;
        const int r = flat >> 6, d = flat & 63;
        float4 v = *(const float4*)&Qp[(size_t)(qbase + r)*DH + d];
        Qs[(d+0)*128 + r] = v.x; Qs[(d+1)*128 + r] = v.y;
        Qs[(d+2)*128 + r] = v.z; Qs[(d+3)*128 + r] = v.w;
    }

    float m[8], l[8], o[8][8];
#pragma unroll
    for (int i = 0; i < 8; ++i) {
        m[i] = -1e30f; l[i] = 0.f;
#pragma unroll
        for (int j = 0; j < 8; ++j) o[i][j] = 0.f;
    }

    const int lastKt = 2*qtile + 1;
    for (int kt = 0; kt <= lastKt; ++kt) {
        const int kbase = kt * 64;
        __syncthreads();

#pragma unroll
        for (int p = 0; p < 8; ++p) {
            const int flat = (tid + p*128) * 4;
            const int r = flat >> 6, d = flat & 63;
            float4 kv = *(const float4*)&Kp[(size_t)(kbase + r)*DH + d];
            KP[(d+0)*64 + r] = kv.x; KP[(d+1)*64 + r] = kv.y;
            KP[(d+2)*64 + r] = kv.z; KP[(d+3)*64 + r] = kv.w;
            float4 vv = *(const float4*)&Vp[(size_t)(kbase + r)*DH + d];
            *(float4*)&Vs[r*64 + d] = vv;
        }
        __syncthreads();

        float s[8][8];
#pragma unroll
        for (int i = 0; i < 8; ++i)
#pragma unroll
            for (int j = 0; j < 8; ++j) s[i][j] = 0.f;

#pragma unroll 8
        for (int kk = 0; kk < 64; ++kk) {
            float a[8], b[8];
            *(float4*)(a)   = *(const float4*)&Qs[kk*128 + ty*8];
            *(float4*)(a+4) = *(const float4*)&Qs[kk*128 + ty*8 + 4];
            *(float4*)(b)   = *(const float4*)&KP[kk*64 + tx*8];
            *(float4*)(b+4) = *(const float4*)&KP[kk*64 + tx*8 + 4];
#pragma unroll
            for (int i = 0; i < 8; ++i)
#pragma unroll
                for (int j = 0; j < 8; ++j)
                    s[i][j] = fmaf(a[i], b[j], s[i][j]);
        }

        const float sc = 0.125f;
        if (kbase + 63 > qbase) {
#pragma unroll
            for (int i = 0; i < 8; ++i) {
                const int qi = qbase + ty*8 + i;
#pragma unroll
                for (int j = 0; j < 8; ++j) {
                    const int kj = kbase + tx*8 + j;
                    s[i][j] = (kj <= qi) ? s[i][j]*sc : -1e30f;
                }
            }
        } else {
#pragma unroll
            for (int i = 0; i < 8; ++i)
#pragma unroll
                for (int j = 0; j < 8; ++j) s[i][j] *= sc;
        }

#pragma unroll
        for (int i = 0; i < 8; ++i) {
            float mx = s[i][0];
#pragma unroll
            for (int j = 1; j < 8; ++j) mx = fmaxf(mx, s[i][j]);
            mx = fmaxf(mx, __shfl_xor_sync(0xffffffffu, mx, 1));
            mx = fmaxf(mx, __shfl_xor_sync(0xffffffffu, mx, 2));
            mx = fmaxf(mx, __shfl_xor_sync(0xffffffffu, mx, 4));
            const float mn = fmaxf(m[i], mx);
            const float al = expf(m[i] - mn);
            m[i] = mn;
            float rs = 0.f;
#pragma unroll
            for (int j = 0; j < 8; ++j) { s[i][j] = expf(s[i][j] - mn); rs += s[i][j]; }
            rs += __shfl_xor_sync(0xffffffffu, rs, 1);
            rs += __shfl_xor_sync(0xffffffffu, rs, 2);
            rs += __shfl_xor_sync(0xffffffffu, rs, 4);
            l[i] = l[i]*al + rs;
#pragma unroll
            for (int j = 0; j < 8; ++j) o[i][j] *= al;
        }

        __syncthreads();
#pragma unroll
        for (int j = 0; j < 8; ++j) {
            float4 p0 = make_float4(s[0][j], s[1][j], s[2][j], s[3][j]);
            float4 p1 = make_float4(s[4][j], s[5][j], s[6][j], s[7][j]);
            *(float4*)&KP[(tx*8+j)*128 + ty*8]     = p0;
            *(float4*)&KP[(tx*8+j)*128 + ty*8 + 4] = p1;
        }
        __syncthreads();

#pragma unroll 8
        for (int kk = 0; kk < 64; ++kk) {
            float a[8], b[8];
            *(float4*)(a)   = *(const float4*)&KP[kk*128 + ty*8];
            *(float4*)(a+4) = *(const float4*)&KP[kk*128 + ty*8 + 4];
            *(float4*)(b)   = *(const float4*)&Vs[kk*64 + tx*8];
            *(float4*)(b+4) = *(const float4*)&Vs[kk*64 + tx*8 + 4];
#pragma unroll
            for (int i = 0; i < 8; ++i)
#pragma unroll
                for (int j = 0; j < 8; ++j)
                    o[i][j] = fmaf(a[i], b[j], o[i][j]);
        }
    }

    const int b = bh / NH, hh = bh % NH;
#pragma unroll
    for (int i = 0; i < 8; ++i) {
        const float inv = 1.f / l[i];
        const int t = qbase + ty*8 + i;
        float* dst = &Ao[((size_t)(b*TT + t))*DD + hh*DH + tx*8];
        float4 v0 = make_float4(o[i][0]*inv, o[i][1]*inv, o[i][2]*inv, o[i][3]*inv);
        float4 v1 = make_float4(o[i][4]*inv, o[i][5]*inv, o[i][6]*inv, o[i][7]*inv);
        *(float4*)(dst)     = v0;
        *(float4*)(dst + 4) = v1;
    }
}

// ---------------------------------------------------------------------------
extern "C" void kernel_launch(void* const* d_in, const int* in_sizes, int n_in,
                              void* d_out, int out_size)
{
    const float* h  = (const float*)d_in[0];
    const float* wq = (const float*)d_in[1];
    const float* wk = (const float*)d_in[2];
    const float* wv = (const float*)d_in[3];
    const float* wo = (const float*)d_in[4];
    float* out = (float*)d_out;
    (void)in_sizes; (void)n_in; (void)out_size;

    float *pQ, *pK, *pV, *pA;
    cudaGetSymbolAddress((void**)&pQ, g_Q);
    cudaGetSymbolAddress((void**)&pK, g_K);
    cudaGetSymbolAddress((void**)&pV, g_V);
    cudaGetSymbolAddress((void**)&pA, g_A);

    cudaFuncSetAttribute(flash_attn, cudaFuncAttributeMaxDynamicSharedMemorySize, 81920);

    const dim3 ggrid(DD/128, BT/128);   // (8, 32)
    tgemm_nt<1><<<ggrid, 256>>>(h, wq, pQ, BT, DD, DD);
    tgemm_nt<1><<<ggrid, 256>>>(h, wk, pK, BT, DD, DD);
    tgemm_nt<1><<<ggrid, 256>>>(h, wv, pV, BT, DD, DD);

    const int nrope = BB*NH*TT*(DH/2);          // 2,097,152
    rope_kernel<<<nrope/256, 256>>>(pQ, pK);

    flash_attn<<<dim3(TT/128, BB*NH), 128, 81920>>>(pQ, pK, pV, pA);

    tgemm_nt<0><<<ggrid, 256>>>(pA, wo, out, BT, DD, DD);
}

// round 4
// speedup vs baseline: 1.7353x; 1.0981x over previous
#include <cuda_runtime.h>
#include <math.h>

#define BB 2
#define TT 2048
#define DD 1024
#define NH 16
#define DH 64
#define BT (BB*TT)

// Scratch (allocation-free rule: __device__ globals)
__device__ float g_Q[BB*NH*TT*DH];   // [b,h,t,d]
__device__ float g_K[BB*NH*TT*DH];
__device__ float g_V[BB*NH*TT*DH];
__device__ float g_A[BT*DD];         // [b,t,h*dh]

__device__ __forceinline__ unsigned f2tf32(float x) {
    unsigned r;
    asm("cvt.rna.tf32.f32 %0, %1;" : "=r"(r) : "f"(x));
    return r;
}

#define MMA_TF32(d0,d1,d2,d3,a0,a1,a2,a3,b0,b1)                                   \
    asm volatile("mma.sync.aligned.m16n8k8.row.col.f32.tf32.tf32.f32 "            \
                 "{%0,%1,%2,%3},{%4,%5,%6,%7},{%8,%9},{%0,%1,%2,%3};"             \
                 : "+f"(d0), "+f"(d1), "+f"(d2), "+f"(d3)                         \
                 : "r"(a0), "r"(a1), "r"(a2), "r"(a3), "r"(b0), "r"(b1))

// ---------------------------------------------------------------------------
// tf32 tensor-core GEMM NT: C[M,N] = A[M,K] * W[N,K]^T  (row-major, K contig)
// MODE 0: C row-major [M,N];  MODE 1: scatter into head layout [b,h,t,d]
// ---------------------------------------------------------------------------
template<int MODE>
__global__ __launch_bounds__(256)
void tgemm_nt(const float* __restrict__ A, const float* __restrict__ W,
              float* __restrict__ C, int M, int N, int K)
{
    __shared__ unsigned As[16][136];
    __shared__ unsigned Bs[16][136];

    const int tid = threadIdx.x;
    const int lane = tid & 31;
    const int warp = tid >> 5;
    const int grp = lane >> 2;
    const int qk  = lane & 3;
    const int warpM = (warp & 1) * 64;
    const int warpN = (warp >> 1) * 32;
    const int rowBase = blockIdx.y * 128;
    const int colBase = blockIdx.x * 128;

    float acc[4][4][4];
#pragma unroll
    for (int mt = 0; mt < 4; ++mt)
#pragma unroll
        for (int nt = 0; nt < 4; ++nt)
#pragma unroll
            for (int r = 0; r < 4; ++r) acc[mt][nt][r] = 0.f;

    const int lr = tid >> 1;
    const int lk = (tid & 1) << 2;
    const float* Ap = A + (size_t)(rowBase + lr) * K + lk;
    const float* Wp = W + (size_t)(colBase + lr) * K + lk;

    for (int k0 = 0; k0 < K; k0 += 16) {
        float4 a0v = *(const float4*)(Ap + k0);
        float4 a1v = *(const float4*)(Ap + k0 + 8);
        float4 b0v = *(const float4*)(Wp + k0);
        float4 b1v = *(const float4*)(Wp + k0 + 8);
        __syncthreads();
        As[lk+0][lr] = f2tf32(a0v.x); As[lk+1][lr] = f2tf32(a0v.y);
        As[lk+2][lr] = f2tf32(a0v.z); As[lk+3][lr] = f2tf32(a0v.w);
        As[lk+8][lr] = f2tf32(a1v.x); As[lk+9][lr] = f2tf32(a1v.y);
        As[lk+10][lr]= f2tf32(a1v.z); As[lk+11][lr]= f2tf32(a1v.w);
        Bs[lk+0][lr] = f2tf32(b0v.x); Bs[lk+1][lr] = f2tf32(b0v.y);
        Bs[lk+2][lr] = f2tf32(b0v.z); Bs[lk+3][lr] = f2tf32(b0v.w);
        Bs[lk+8][lr] = f2tf32(b1v.x); Bs[lk+9][lr] = f2tf32(b1v.y);
        Bs[lk+10][lr]= f2tf32(b1v.z); Bs[lk+11][lr]= f2tf32(b1v.w);
        __syncthreads();

#pragma unroll
        for (int ks = 0; ks < 2; ++ks) {
            const int kb = ks * 8;
            unsigned af[4][4], bf[4][2];
#pragma unroll
            for (int mt = 0; mt < 4; ++mt) {
                const int m0 = warpM + mt*16 + grp;
                af[mt][0] = As[kb + qk    ][m0];
                af[mt][1] = As[kb + qk    ][m0 + 8];
                af[mt][2] = As[kb + 4 + qk][m0];
                af[mt][3] = As[kb + 4 + qk][m0 + 8];
            }
#pragma unroll
            for (int nt = 0; nt < 4; ++nt) {
                const int n0 = warpN + nt*8 + grp;
                bf[nt][0] = Bs[kb + qk    ][n0];
                bf[nt][1] = Bs[kb + 4 + qk][n0];
            }
#pragma unroll
            for (int mt = 0; mt < 4; ++mt)
#pragma unroll
                for (int nt = 0; nt < 4; ++nt)
                    MMA_TF32(acc[mt][nt][0], acc[mt][nt][1],
                             acc[mt][nt][2], acc[mt][nt][3],
                             af[mt][0], af[mt][1], af[mt][2], af[mt][3],
                             bf[nt][0], bf[nt][1]);
        }
    }

#pragma unroll
    for (int mt = 0; mt < 4; ++mt) {
#pragma unroll
        for (int nt = 0; nt < 4; ++nt) {
            const int r0 = rowBase + warpM + mt*16 + grp;
            const int c  = colBase + warpN + nt*8 + 2*qk;
            float2 v0 = make_float2(acc[mt][nt][0], acc[mt][nt][1]);
            float2 v1 = make_float2(acc[mt][nt][2], acc[mt][nt][3]);
            if (MODE == 0) {
                *(float2*)&C[(size_t)r0 * N + c]     = v0;
                *(float2*)&C[(size_t)(r0+8) * N + c] = v1;
            } else {
                const int h = c / DH, d = c % DH;
                const int b0 = r0 / TT, t0 = r0 % TT;
                const int b1 = (r0+8) / TT, t1 = (r0+8) % TT;
                *(float2*)&C[(((size_t)(b0*NH + h))*TT + t0)*DH + d] = v0;
                *(float2*)&C[(((size_t)(b1*NH + h))*TT + t1)*DH + d] = v1;
            }
        }
    }
}

// ---------------------------------------------------------------------------
// RoPE on interleaved pairs, in-place on Q and K ([b,h,t,d] layout)
// ---------------------------------------------------------------------------
__global__ void rope_kernel(float* __restrict__ Q, float* __restrict__ K)
{
    const int id = blockIdx.x * blockDim.x + threadIdx.x;
    const int pair = id & 31;
    const int rest = id >> 5;
    const int t  = rest % TT;
    const int bh = rest / TT;
    const size_t base = ((size_t)bh * TT + t) * DH + 2*pair;

    const float freq = powf(10000.0f, -(float)pair * (1.0f/32.0f));
    const float ang = (float)t * freq;
    float s, c;
    sincosf(ang, &s, &c);

    float q0 = Q[base], q1 = Q[base+1];
    Q[base]   = c*q0 - s*q1;
    Q[base+1] = s*q0 + c*q1;
    float k0 = K[base], k1 = K[base+1];
    K[base]   = c*k0 - s*k1;
    K[base+1] = s*k0 + c*k1;
}

// ---------------------------------------------------------------------------
// Tensor-core (tf32) causal flash attention.
// BM=128 (8 warps x 16 rows), BN=64, dh=64, 256 threads.
// Q in registers (A-fragment layout). K,V plain row-major smem, stride 68
// (QK^T B-gathers conflict-free; PV B-gathers <=2-way). P per-warp smem slice.
// Smem: Ks 64x68 | Vs 64x68 | Ps 8x16x68  (uint words) = 69632 B.
// ---------------------------------------------------------------------------
#define KST 68

__global__ __launch_bounds__(256)
void flash_tc(const float* __restrict__ Q, const float* __restrict__ K,
              const float* __restrict__ V, float* __restrict__ Ao)
{
    extern __shared__ unsigned smu[];
    unsigned* Ks = smu;                    // [64][KST]
    unsigned* Vs = smu + 64*KST;           // [64][KST]
    unsigned* Ps = smu + 2*64*KST;         // [8][16][KST]

    const int tid  = threadIdx.x;
    const int lane = tid & 31;
    const int warp = tid >> 5;
    const int grp  = lane >> 2;            // 0..7
    const int qk   = lane & 3;             // 0..3
    const int qtile = gridDim.x - 1 - blockIdx.x;   // heavy tiles first
    const int bh    = blockIdx.y;
    const int qbase = qtile * 128;
    const int warpRow = warp * 16;

    const float* Qp = Q + (size_t)bh * TT * DH;
    const float* Kp = K + (size_t)bh * TT * DH;
    const float* Vp = V + (size_t)bh * TT * DH;

    // ---- Q fragments in registers (rows qi0=base+grp, qi1=+8; cols qk+4j) --
    const int qi0 = qbase + warpRow + grp;
    const int qi1 = qi0 + 8;
    unsigned qa0[16], qa1[16];
    {
        const float* q0 = Qp + (size_t)qi0 * DH + qk;
        const float* q1 = Qp + (size_t)qi1 * DH + qk;
#pragma unroll
        for (int j = 0; j < 16; ++j) {
            qa0[j] = f2tf32(q0[4*j]);
            qa1[j] = f2tf32(q1[4*j]);
        }
    }

    float m0 = -1e30f, m1 = -1e30f, l0 = 0.f, l1 = 0.f;
    float oa[8][4];
#pragma unroll
    for (int nt = 0; nt < 8; ++nt)
#pragma unroll
        for (int r = 0; r < 4; ++r) oa[nt][r] = 0.f;

    // K/V loader mapping: row = tid>>2 (0..63), 16 floats starting at (tid&3)*16
    const int ldRow = tid >> 2;
    const int ldD0  = (tid & 3) * 16;

    const int lastKt = 2*qtile + 1;
    for (int kt = 0; kt <= lastKt; ++kt) {
        const int kbase = kt * 64;
        __syncthreads();
        {
            const float4* kg = (const float4*)&Kp[(size_t)(kbase + ldRow)*DH + ldD0];
            const float4* vg = (const float4*)&Vp[(size_t)(kbase + ldRow)*DH + ldD0];
            unsigned* kd = &Ks[ldRow*KST + ldD0];
            unsigned* vd = &Vs[ldRow*KST + ldD0];
#pragma unroll
            for (int c = 0; c < 4; ++c) {
                float4 kv = kg[c];
                kd[4*c+0] = f2tf32(kv.x); kd[4*c+1] = f2tf32(kv.y);
                kd[4*c+2] = f2tf32(kv.z); kd[4*c+3] = f2tf32(kv.w);
                float4 vv = vg[c];
                vd[4*c+0] = f2tf32(vv.x); vd[4*c+1] = f2tf32(vv.y);
                vd[4*c+2] = f2tf32(vv.z); vd[4*c+3] = f2tf32(vv.w);
            }
        }
        __syncthreads();

        // ---- S = Q K^T ----
        float sa[8][4];
#pragma unroll
        for (int nt = 0; nt < 8; ++nt)
#pragma unroll
            for (int r = 0; r < 4; ++r) sa[nt][r] = 0.f;

#pragma unroll
        for (int ks = 0; ks < 8; ++ks) {
            const unsigned a0 = qa0[2*ks], a2 = qa0[2*ks+1];
            const unsigned a1 = qa1[2*ks], a3 = qa1[2*ks+1];
#pragma unroll
            for (int nt = 0; nt < 8; ++nt) {
                const unsigned* kb = &Ks[(nt*8 + grp)*KST + ks*8 + qk];
                MMA_TF32(sa[nt][0], sa[nt][1], sa[nt][2], sa[nt][3],
                         a0, a1, a2, a3, kb[0], kb[4]);
            }
        }

        // ---- scale + causal mask ----
        const float sc = 0.125f;   // 1/sqrt(64)
        if (kbase + 63 > qbase) {
#pragma unroll
            for (int nt = 0; nt < 8; ++nt) {
                const int c0 = kbase + nt*8 + 2*qk;
                const int c1 = c0 + 1;
                sa[nt][0] = (c0 <= qi0) ? sa[nt][0]*sc : -1e30f;
                sa[nt][1] = (c1 <= qi0) ? sa[nt][1]*sc : -1e30f;
                sa[nt][2] = (c0 <= qi1) ? sa[nt][2]*sc : -1e30f;
                sa[nt][3] = (c1 <= qi1) ? sa[nt][3]*sc : -1e30f;
            }
        } else {
#pragma unroll
            for (int nt = 0; nt < 8; ++nt)
#pragma unroll
                for (int r = 0; r < 4; ++r) sa[nt][r] *= sc;
        }

        // ---- online softmax (row = quad; reduce with 2 shfls) ----
        float mx0 = sa[0][0], mx1 = sa[0][2];
#pragma unroll
        for (int nt = 0; nt < 8; ++nt) {
            mx0 = fmaxf(mx0, fmaxf(sa[nt][0], sa[nt][1]));
            mx1 = fmaxf(mx1, fmaxf(sa[nt][2], sa[nt][3]));
        }
        mx0 = fmaxf(mx0, __shfl_xor_sync(0xffffffffu, mx0, 1));
        mx0 = fmaxf(mx0, __shfl_xor_sync(0xffffffffu, mx0, 2));
        mx1 = fmaxf(mx1, __shfl_xor_sync(0xffffffffu, mx1, 1));
        mx1 = fmaxf(mx1, __shfl_xor_sync(0xffffffffu, mx1, 2));

        const float nm0 = fmaxf(m0, mx0);
        const float nm1 = fmaxf(m1, mx1);
        const float al0 = __expf(m0 - nm0);
        const float al1 = __expf(m1 - nm1);
        m0 = nm0; m1 = nm1;

        float rs0 = 0.f, rs1 = 0.f;
#pragma unroll
        for (int nt = 0; nt < 8; ++nt) {
            sa[nt][0] = __expf(sa[nt][0] - nm0);
            sa[nt][1] = __expf(sa[nt][1] - nm0);
            sa[nt][2] = __expf(sa[nt][2] - nm1);
            sa[nt][3] = __expf(sa[nt][3] - nm1);
            rs0 += sa[nt][0] + sa[nt][1];
            rs1 += sa[nt][2] + sa[nt][3];
        }
        rs0 += __shfl_xor_sync(0xffffffffu, rs0, 1);
        rs0 += __shfl_xor_sync(0xffffffffu, rs0, 2);
        rs1 += __shfl_xor_sync(0xffffffffu, rs1, 1);
        rs1 += __shfl_xor_sync(0xffffffffu, rs1, 2);
        l0 = l0*al0 + rs0;
        l1 = l1*al1 + rs1;

#pragma unroll
        for (int nt = 0; nt < 8; ++nt) {
            oa[nt][0] *= al0; oa[nt][1] *= al0;
            oa[nt][2] *= al1; oa[nt][3] *= al1;
        }

        // ---- P -> per-warp smem slice (tf32), then O += P V ----
        unsigned* Pw = Ps + warp * 16 * KST;
        __syncwarp();
#pragma unroll
        for (int nt = 0; nt < 8; ++nt) {
            uint2 p0 = make_uint2(f2tf32(sa[nt][0]), f2tf32(sa[nt][1]));
            uint2 p1 = make_uint2(f2tf32(sa[nt][2]), f2tf32(sa[nt][3]));
            *(uint2*)&Pw[ grp     *KST + nt*8 + 2*qk] = p0;
            *(uint2*)&Pw[(grp+8)*KST + nt*8 + 2*qk] = p1;
        }
        __syncwarp();

#pragma unroll
        for (int ks = 0; ks < 8; ++ks) {
            const unsigned a0 = Pw[ grp    *KST + ks*8 + qk];
            const unsigned a1 = Pw[(grp+8)*KST + ks*8 + qk];
            const unsigned a2 = Pw[ grp    *KST + ks*8 + qk + 4];
            const unsigned a3 = Pw[(grp+8)*KST + ks*8 + qk + 4];
#pragma unroll
            for (int nt = 0; nt < 8; ++nt) {
                const unsigned b0 = Vs[(ks*8 + qk    )*KST + nt*8 + grp];
                const unsigned b1 = Vs[(ks*8 + qk + 4)*KST + nt*8 + grp];
                MMA_TF32(oa[nt][0], oa[nt][1], oa[nt][2], oa[nt][3],
                         a0, a1, a2, a3, b0, b1);
            }
        }
    }

    // ---- epilogue: normalize, write to [b, t, h*dh] ----
    const int b = bh / NH, hh = bh % NH;
    const float inv0 = 1.f / l0;
    const float inv1 = 1.f / l1;
    float* d0 = &Ao[((size_t)(b*TT + qi0))*DD + hh*DH];
    float* d1 = &Ao[((size_t)(b*TT + qi1))*DD + hh*DH];
#pragma unroll
    for (int nt = 0; nt < 8; ++nt) {
        const int c = nt*8 + 2*qk;
        *(float2*)&d0[c] = make_float2(oa[nt][0]*inv0, oa[nt][1]*inv0);
        *(float2*)&d1[c] = make_float2(oa[nt][2]*inv1, oa[nt][3]*inv1);
    }
}

// ---------------------------------------------------------------------------
extern "C" void kernel_launch(void* const* d_in, const int* in_sizes, int n_in,
                              void* d_out, int out_size)
{
    const float* h  = (const float*)d_in[0];
    const float* wq = (const float*)d_in[1];
    const float* wk = (const float*)d_in[2];
    const float* wv = (const float*)d_in[3];
    const float* wo = (const float*)d_in[4];
    float* out = (float*)d_out;
    (void)in_sizes; (void)n_in; (void)out_size;

    float *pQ, *pK, *pV, *pA;
    cudaGetSymbolAddress((void**)&pQ, g_Q);
    cudaGetSymbolAddress((void**)&pK, g_K);
    cudaGetSymbolAddress((void**)&pV, g_V);
    cudaGetSymbolAddress((void**)&pA, g_A);

    const int smem = (2*64*KST + 8*16*KST) * 4;   // 69632 B
    cudaFuncSetAttribute(flash_tc, cudaFuncAttributeMaxDynamicSharedMemorySize, smem);

    const dim3 ggrid(DD/128, BT/128);   // (8, 32)
    tgemm_nt<1><<<ggrid, 256>>>(h, wq, pQ, BT, DD, DD);
    tgemm_nt<1><<<ggrid, 256>>>(h, wk, pK, BT, DD, DD);
    tgemm_nt<1><<<ggrid, 256>>>(h, wv, pV, BT, DD, DD);

    const int nrope = BB*NH*TT*(DH/2);
    rope_kernel<<<nrope/256, 256>>>(pQ, pK);

    flash_tc<<<dim3(TT/128, BB*NH), 256, smem>>>(pQ, pK, pV, pA);

    tgemm_nt<0><<<ggrid, 256>>>(pA, wo, out, BT, DD, DD);
}

// round 5
// speedup vs baseline: 3.2210x; 1.8561x over previous
#include <cuda_runtime.h>
#include <cuda_fp16.h>
#include <math.h>

#define BB 2
#define TT 2048
#define DD 1024
#define NH 16
#define DH 64
#define BT (BB*TT)

// Scratch (allocation-free rule: __device__ globals)
__device__ float g_Q[BB*NH*TT*DH];   // [b,h,t,d]
__device__ float g_K[BB*NH*TT*DH];
__device__ float g_V[BB*NH*TT*DH];
__device__ float g_A[BT*DD];         // [b,t,h*dh]

__device__ __forceinline__ unsigned f2tf32(float x) {
    unsigned r;
    asm("cvt.rna.tf32.f32 %0, %1;" : "=r"(r) : "f"(x));
    return r;
}

// pack two floats into half2 register: lo = x, hi = y
__device__ __forceinline__ unsigned pack_h2(float x, float y) {
    unsigned r;
    asm("cvt.rn.f16x2.f32 %0, %1, %2;" : "=r"(r) : "f"(y), "f"(x));
    return r;
}

#define MMA_TF32(d0,d1,d2,d3,a0,a1,a2,a3,b0,b1)                                   \
    asm volatile("mma.sync.aligned.m16n8k8.row.col.f32.tf32.tf32.f32 "            \
                 "{%0,%1,%2,%3},{%4,%5,%6,%7},{%8,%9},{%0,%1,%2,%3};"             \
                 : "+f"(d0), "+f"(d1), "+f"(d2), "+f"(d3)                         \
                 : "r"(a0), "r"(a1), "r"(a2), "r"(a3), "r"(b0), "r"(b1))

#define MMA_F16(d0,d1,d2,d3,a0,a1,a2,a3,b0,b1)                                    \
    asm volatile("mma.sync.aligned.m16n8k16.row.col.f32.f16.f16.f32 "             \
                 "{%0,%1,%2,%3},{%4,%5,%6,%7},{%8,%9},{%0,%1,%2,%3};"             \
                 : "+f"(d0), "+f"(d1), "+f"(d2), "+f"(d3)                         \
                 : "r"(a0), "r"(a1), "r"(a2), "r"(a3), "r"(b0), "r"(b1))

#define LDSM_X4_TRANS(r0,r1,r2,r3,addr)                                           \
    asm volatile("ldmatrix.sync.aligned.m8n8.x4.trans.shared.b16 "                \
                 "{%0,%1,%2,%3}, [%4];"                                           \
                 : "=r"(r0), "=r"(r1), "=r"(r2), "=r"(r3) : "r"(addr))

// ---------------------------------------------------------------------------
// Shared tf32 GEMM body: C-scatter handled by caller lambda-like epilogue.
// Computes 128x128 tile of A[M,K] * W[N,K]^T.
// ---------------------------------------------------------------------------
template<int MODE>
__device__ __forceinline__
void gemm_body(const float* __restrict__ A, const float* __restrict__ W,
               float* __restrict__ C, int K, int N,
               int rowBase, int colBase)
{
    __shared__ unsigned As[16][136];
    __shared__ unsigned Bs[16][136];

    const int tid = threadIdx.x;
    const int lane = tid & 31;
    const int warp = tid >> 5;
    const int grp = lane >> 2;
    const int qk  = lane & 3;
    const int warpM = (warp & 1) * 64;
    const int warpN = (warp >> 1) * 32;

    float acc[4][4][4];
#pragma unroll
    for (int mt = 0; mt < 4; ++mt)
#pragma unroll
        for (int nt = 0; nt < 4; ++nt)
#pragma unroll
            for (int r = 0; r < 4; ++r) acc[mt][nt][r] = 0.f;

    const int lr = tid >> 1;
    const int lk = (tid & 1) << 2;
    const float* Ap = A + (size_t)(rowBase + lr) * K + lk;
    const float* Wp = W + (size_t)(colBase + lr) * K + lk;

    for (int k0 = 0; k0 < K; k0 += 16) {
        float4 a0v = *(const float4*)(Ap + k0);
        float4 a1v = *(const float4*)(Ap + k0 + 8);
        float4 b0v = *(const float4*)(Wp + k0);
        float4 b1v = *(const float4*)(Wp + k0 + 8);
        __syncthreads();
        As[lk+0][lr] = f2tf32(a0v.x); As[lk+1][lr] = f2tf32(a0v.y);
        As[lk+2][lr] = f2tf32(a0v.z); As[lk+3][lr] = f2tf32(a0v.w);
        As[lk+8][lr] = f2tf32(a1v.x); As[lk+9][lr] = f2tf32(a1v.y);
        As[lk+10][lr]= f2tf32(a1v.z); As[lk+11][lr]= f2tf32(a1v.w);
        Bs[lk+0][lr] = f2tf32(b0v.x); Bs[lk+1][lr] = f2tf32(b0v.y);
        Bs[lk+2][lr] = f2tf32(b0v.z); Bs[lk+3][lr] = f2tf32(b0v.w);
        Bs[lk+8][lr] = f2tf32(b1v.x); Bs[lk+9][lr] = f2tf32(b1v.y);
        Bs[lk+10][lr]= f2tf32(b1v.z); Bs[lk+11][lr]= f2tf32(b1v.w);
        __syncthreads();

#pragma unroll
        for (int ks = 0; ks < 2; ++ks) {
            const int kb = ks * 8;
            unsigned af[4][4], bf[4][2];
#pragma unroll
            for (int mt = 0; mt < 4; ++mt) {
                const int m0 = warpM + mt*16 + grp;
                af[mt][0] = As[kb + qk    ][m0];
                af[mt][1] = As[kb + qk    ][m0 + 8];
                af[mt][2] = As[kb + 4 + qk][m0];
                af[mt][3] = As[kb + 4 + qk][m0 + 8];
            }
#pragma unroll
            for (int nt = 0; nt < 4; ++nt) {
                const int n0 = warpN + nt*8 + grp;
                bf[nt][0] = Bs[kb + qk    ][n0];
                bf[nt][1] = Bs[kb + 4 + qk][n0];
            }
#pragma unroll
            for (int mt = 0; mt < 4; ++mt)
#pragma unroll
                for (int nt = 0; nt < 4; ++nt)
                    MMA_TF32(acc[mt][nt][0], acc[mt][nt][1],
                             acc[mt][nt][2], acc[mt][nt][3],
                             af[mt][0], af[mt][1], af[mt][2], af[mt][3],
                             bf[nt][0], bf[nt][1]);
        }
    }

#pragma unroll
    for (int mt = 0; mt < 4; ++mt) {
#pragma unroll
        for (int nt = 0; nt < 4; ++nt) {
            const int r0 = rowBase + warpM + mt*16 + grp;
            const int c  = colBase + warpN + nt*8 + 2*qk;
            float2 v0 = make_float2(acc[mt][nt][0], acc[mt][nt][1]);
            float2 v1 = make_float2(acc[mt][nt][2], acc[mt][nt][3]);
            if (MODE == 0) {
                *(float2*)&C[(size_t)r0 * N + c]     = v0;
                *(float2*)&C[(size_t)(r0+8) * N + c] = v1;
            } else {
                const int h = c / DH, d = c % DH;
                const int b0 = r0 / TT, t0 = r0 % TT;
                const int b1 = (r0+8) / TT, t1 = (r0+8) % TT;
                *(float2*)&C[(((size_t)(b0*NH + h))*TT + t0)*DH + d] = v0;
                *(float2*)&C[(((size_t)(b1*NH + h))*TT + t1)*DH + d] = v1;
            }
        }
    }
}

// QKV fused: grid.z selects which projection; scatter into head layout.
__global__ __launch_bounds__(256)
void tgemm_qkv(const float* __restrict__ h,
               const float* __restrict__ wq, const float* __restrict__ wk,
               const float* __restrict__ wv,
               float* __restrict__ Qo, float* __restrict__ Ko, float* __restrict__ Vo)
{
    const float* W = (blockIdx.z == 0) ? wq : (blockIdx.z == 1) ? wk : wv;
    float*       C = (blockIdx.z == 0) ? Qo : (blockIdx.z == 1) ? Ko : Vo;
    gemm_body<1>(h, W, C, DD, DD, blockIdx.y * 128, blockIdx.x * 128);
}

// Out-projection: plain row-major C.
__global__ __launch_bounds__(256)
void tgemm_out(const float* __restrict__ A, const float* __restrict__ W,
               float* __restrict__ C)
{
    gemm_body<0>(A, W, C, DD, DD, blockIdx.y * 128, blockIdx.x * 128);
}

// ---------------------------------------------------------------------------
// RoPE on interleaved pairs, in-place on Q and K ([b,h,t,d] layout)
// ---------------------------------------------------------------------------
__global__ void rope_kernel(float* __restrict__ Q, float* __restrict__ K)
{
    const int id = blockIdx.x * blockDim.x + threadIdx.x;
    const int pair = id & 31;
    const int rest = id >> 5;
    const int t  = rest % TT;
    const int bh = rest / TT;
    const size_t base = ((size_t)bh * TT + t) * DH + 2*pair;

    const float freq = powf(10000.0f, -(float)pair * (1.0f/32.0f));
    const float ang = (float)t * freq;
    float s, c;
    sincosf(ang, &s, &c);

    float q0 = Q[base], q1 = Q[base+1];
    Q[base]   = c*q0 - s*q1;
    Q[base+1] = s*q0 + c*q1;
    float k0 = K[base], k1 = K[base+1];
    K[base]   = c*k0 - s*k1;
    K[base+1] = s*k0 + c*k1;
}

// ---------------------------------------------------------------------------
// Tensor-core causal flash attention.
// QK^T: tf32 m16n8k8 (Q in registers, K tf32 smem stride 68, conflict-free).
// PV:   fp16 m16n8k16 — P packed IN-REGISTER from S accumulators (no smem
//       round-trip), V fp16 smem read via ldmatrix.x4.trans.
// BM=128 (8 warps x 16 rows), BN=64, dh=64, 256 threads.
// Smem: Ks[64][68] u32 (17408B) + Vh[64][36] u32-as-half2 (9216B) = 26.6KB.
// ---------------------------------------------------------------------------
#define KST  68
#define VSTH 72   // halves per V row
#define VSTU 36   // uints per V row

__global__ __launch_bounds__(256, 2)
void flash_tc(const float* __restrict__ Q, const float* __restrict__ K,
              const float* __restrict__ V, float* __restrict__ Ao)
{
    __shared__ unsigned Ks[64*KST];
    __shared__ unsigned Vh[64*VSTU];

    const int tid  = threadIdx.x;
    const int lane = tid & 31;
    const int warp = tid >> 5;
    const int grp  = lane >> 2;            // 0..7
    const int qk   = lane & 3;             // 0..3
    const int qtile = gridDim.x - 1 - blockIdx.x;   // heavy tiles first
    const int bh    = blockIdx.y;
    const int qbase = qtile * 128;
    const int warpRow = warp * 16;

    const float* Qp = Q + (size_t)bh * TT * DH;
    const float* Kp = K + (size_t)bh * TT * DH;
    const float* Vp = V + (size_t)bh * TT * DH;

    const unsigned vbase = (unsigned)__cvta_generic_to_shared(Vh);
    // ldmatrix lane mapping for x4.trans: 4 8x8 matrices (k0-7/k8-15 x n0-7/n8-15)
    const int lm_row = lane & 15;          // row within 16-wide k-chunk
    const int lm_col = (lane >> 4) * 8;    // 0 or 8

    // ---- Q fragments in registers (rows qi0=base+grp, qi1=+8; cols qk+4j) --
    const int qi0 = qbase + warpRow + grp;
    const int qi1 = qi0 + 8;
    unsigned qa0[16], qa1[16];
    {
        const float* q0 = Qp + (size_t)qi0 * DH + qk;
        const float* q1 = Qp + (size_t)qi1 * DH + qk;
#pragma unroll
        for (int j = 0; j < 16; ++j) {
            qa0[j] = f2tf32(q0[4*j]);
            qa1[j] = f2tf32(q1[4*j]);
        }
    }

    float m0 = -1e30f, m1 = -1e30f, l0 = 0.f, l1 = 0.f;
    float oa[8][4];
#pragma unroll
    for (int nt = 0; nt < 8; ++nt)
#pragma unroll
        for (int r = 0; r < 4; ++r) oa[nt][r] = 0.f;

    // K/V loader mapping: row = tid>>2 (0..63), 16 floats from (tid&3)*16
    const int ldRow = tid >> 2;
    const int ldD0  = (tid & 3) * 16;

    const int lastKt = 2*qtile + 1;
    for (int kt = 0; kt <= lastKt; ++kt) {
        const int kbase = kt * 64;
        __syncthreads();
        {
            const float4* kg = (const float4*)&Kp[(size_t)(kbase + ldRow)*DH + ldD0];
            const float4* vg = (const float4*)&Vp[(size_t)(kbase + ldRow)*DH + ldD0];
            unsigned* kd = &Ks[ldRow*KST + ldD0];
            unsigned* vd = &Vh[ldRow*VSTU + (ldD0 >> 1)];
#pragma unroll
            for (int c = 0; c < 4; ++c) {
                float4 kv = kg[c];
                kd[4*c+0] = f2tf32(kv.x); kd[4*c+1] = f2tf32(kv.y);
                kd[4*c+2] = f2tf32(kv.z); kd[4*c+3] = f2tf32(kv.w);
                float4 vv = vg[c];
                vd[2*c+0] = pack_h2(vv.x, vv.y);
                vd[2*c+1] = pack_h2(vv.z, vv.w);
            }
        }
        __syncthreads();

        // ---- S = Q K^T (tf32) ----
        float sa[8][4];
#pragma unroll
        for (int nt = 0; nt < 8; ++nt)
#pragma unroll
            for (int r = 0; r < 4; ++r) sa[nt][r] = 0.f;

#pragma unroll
        for (int ks = 0; ks < 8; ++ks) {
            const unsigned a0 = qa0[2*ks], a2 = qa0[2*ks+1];
            const unsigned a1 = qa1[2*ks], a3 = qa1[2*ks+1];
#pragma unroll
            for (int nt = 0; nt < 8; ++nt) {
                const unsigned* kb = &Ks[(nt*8 + grp)*KST + ks*8 + qk];
                MMA_TF32(sa[nt][0], sa[nt][1], sa[nt][2], sa[nt][3],
                         a0, a1, a2, a3, kb[0], kb[4]);
            }
        }

        // ---- scale + causal mask ----
        const float sc = 0.125f;   // 1/sqrt(64)
        if (kbase + 63 > qbase) {
#pragma unroll
            for (int nt = 0; nt < 8; ++nt) {
                const int c0 = kbase + nt*8 + 2*qk;
                const int c1 = c0 + 1;
                sa[nt][0] = (c0 <= qi0) ? sa[nt][0]*sc : -1e30f;
                sa[nt][1] = (c1 <= qi0) ? sa[nt][1]*sc : -1e30f;
                sa[nt][2] = (c0 <= qi1) ? sa[nt][2]*sc : -1e30f;
                sa[nt][3] = (c1 <= qi1) ? sa[nt][3]*sc : -1e30f;
            }
        } else {
#pragma unroll
            for (int nt = 0; nt < 8; ++nt)
#pragma unroll
                for (int r = 0; r < 4; ++r) sa[nt][r] *= sc;
        }

        // ---- online softmax (row = quad; 2 shfls per reduction) ----
        float mx0 = sa[0][0], mx1 = sa[0][2];
#pragma unroll
        for (int nt = 0; nt < 8; ++nt) {
            mx0 = fmaxf(mx0, fmaxf(sa[nt][0], sa[nt][1]));
            mx1 = fmaxf(mx1, fmaxf(sa[nt][2], sa[nt][3]));
        }
        mx0 = fmaxf(mx0, __shfl_xor_sync(0xffffffffu, mx0, 1));
        mx0 = fmaxf(mx0, __shfl_xor_sync(0xffffffffu, mx0, 2));
        mx1 = fmaxf(mx1, __shfl_xor_sync(0xffffffffu, mx1, 1));
        mx1 = fmaxf(mx1, __shfl_xor_sync(0xffffffffu, mx1, 2));

        const float nm0 = fmaxf(m0, mx0);
        const float nm1 = fmaxf(m1, mx1);
        const float al0 = __expf(m0 - nm0);
        const float al1 = __expf(m1 - nm1);
        m0 = nm0; m1 = nm1;

        float rs0 = 0.f, rs1 = 0.f;
#pragma unroll
        for (int nt = 0; nt < 8; ++nt) {
            sa[nt][0] = __expf(sa[nt][0] - nm0);
            sa[nt][1] = __expf(sa[nt][1] - nm0);
            sa[nt][2] = __expf(sa[nt][2] - nm1);
            sa[nt][3] = __expf(sa[nt][3] - nm1);
            rs0 += sa[nt][0] + sa[nt][1];
            rs1 += sa[nt][2] + sa[nt][3];
        }
        rs0 += __shfl_xor_sync(0xffffffffu, rs0, 1);
        rs0 += __shfl_xor_sync(0xffffffffu, rs0, 2);
        rs1 += __shfl_xor_sync(0xffffffffu, rs1, 1);
        rs1 += __shfl_xor_sync(0xffffffffu, rs1, 2);
        l0 = l0*al0 + rs0;
        l1 = l1*al1 + rs1;

#pragma unroll
        for (int nt = 0; nt < 8; ++nt) {
            oa[nt][0] *= al0; oa[nt][1] *= al0;
            oa[nt][2] *= al1; oa[nt][3] *= al1;
        }

        // ---- O += P V : fp16 m16n8k16, P packed in-register ----
#pragma unroll
        for (int kc = 0; kc < 4; ++kc) {
            // A-frag of P for k-chunk kc (16 keys):
            //   a0=(row grp,  k=2qk,2qk+1)   a1=(row grp+8, same)
            //   a2=(row grp,  k=2qk+8,+9)    a3=(row grp+8, same)
            const unsigned a0 = pack_h2(sa[2*kc  ][0], sa[2*kc  ][1]);
            const unsigned a1 = pack_h2(sa[2*kc  ][2], sa[2*kc  ][3]);
            const unsigned a2 = pack_h2(sa[2*kc+1][0], sa[2*kc+1][1]);
            const unsigned a3 = pack_h2(sa[2*kc+1][2], sa[2*kc+1][3]);
            const unsigned raddr = vbase +
                (((kc*16 + lm_row) * VSTH) + lm_col) * 2;
#pragma unroll
            for (int np = 0; np < 4; ++np) {
                unsigned b0, b1, b2, b3;
                LDSM_X4_TRANS(b0, b1, b2, b3, raddr + np*32);   // +16 halves
                MMA_F16(oa[2*np  ][0], oa[2*np  ][1], oa[2*np  ][2], oa[2*np  ][3],
                        a0, a1, a2, a3, b0, b1);
                MMA_F16(oa[2*np+1][0], oa[2*np+1][1], oa[2*np+1][2], oa[2*np+1][3],
                        a0, a1, a2, a3, b2, b3);
            }
        }
    }

    // ---- epilogue: normalize, write to [b, t, h*dh] ----
    const int b = bh / NH, hh = bh % NH;
    const float inv0 = 1.f / l0;
    const float inv1 = 1.f / l1;
    float* d0 = &Ao[((size_t)(b*TT + qi0))*DD + hh*DH];
    float* d1 = &Ao[((size_t)(b*TT + qi1))*DD + hh*DH];
#pragma unroll
    for (int nt = 0; nt < 8; ++nt) {
        const int c = nt*8 + 2*qk;
        *(float2*)&d0[c] = make_float2(oa[nt][0]*inv0, oa[nt][1]*inv0);
        *(float2*)&d1[c] = make_float2(oa[nt][2]*inv1, oa[nt][3]*inv1);
    }
}

// ---------------------------------------------------------------------------
extern "C" void kernel_launch(void* const* d_in, const int* in_sizes, int n_in,
                              void* d_out, int out_size)
{
    const float* h  = (const float*)d_in[0];
    const float* wq = (const float*)d_in[1];
    const float* wk = (const float*)d_in[2];
    const float* wv = (const float*)d_in[3];
    const float* wo = (const float*)d_in[4];
    float* out = (float*)d_out;
    (void)in_sizes; (void)n_in; (void)out_size;

    float *pQ, *pK, *pV, *pA;
    cudaGetSymbolAddress((void**)&pQ, g_Q);
    cudaGetSymbolAddress((void**)&pK, g_K);
    cudaGetSymbolAddress((void**)&pV, g_V);
    cudaGetSymbolAddress((void**)&pA, g_A);

    const dim3 ggrid(DD/128, BT/128);          // (8, 32)
    tgemm_qkv<<<dim3(DD/128, BT/128, 3), 256>>>(h, wq, wk, wv, pQ, pK, pV);

    const int nrope = BB*NH*TT*(DH/2);
    rope_kernel<<<nrope/256, 256>>>(pQ, pK);

    flash_tc<<<dim3(TT/128, BB*NH), 256>>>(pQ, pK, pV, pA);

    tgemm_out<<<ggrid, 256>>>(pA, wo, out);
}

// round 7
// speedup vs baseline: 4.2555x; 1.3212x over previous
#include <cuda_runtime.h>
#include <cuda_fp16.h>
#include <math.h>

#define BB 2
#define TT 2048
#define DD 1024
#define NH 16
#define DH 64
#define BT (BB*TT)

// Scratch (allocation-free rule: __device__ globals)
__device__ float g_Q[BB*NH*TT*DH];   // [b,h,t,d]
__device__ float g_K[BB*NH*TT*DH];
__device__ float g_V[BB*NH*TT*DH];
__device__ float g_A[BT*DD];         // [b,t,h*dh]

__device__ __forceinline__ unsigned f2tf32(float x) {
    unsigned r;
    asm("cvt.rna.tf32.f32 %0, %1;" : "=r"(r) : "f"(x));
    return r;
}

// pack two floats into half2 register: lo = x, hi = y
__device__ __forceinline__ unsigned pack_h2(float x, float y) {
    unsigned r;
    asm("cvt.rn.f16x2.f32 %0, %1, %2;" : "=r"(r) : "f"(y), "f"(x));
    return r;
}

#define MMA_TF32(d0,d1,d2,d3,a0,a1,a2,a3,b0,b1)                                   \
    asm volatile("mma.sync.aligned.m16n8k8.row.col.f32.tf32.tf32.f32 "            \
                 "{%0,%1,%2,%3},{%4,%5,%6,%7},{%8,%9},{%0,%1,%2,%3};"             \
                 : "+f"(d0), "+f"(d1), "+f"(d2), "+f"(d3)                         \
                 : "r"(a0), "r"(a1), "r"(a2), "r"(a3), "r"(b0), "r"(b1))

#define MMA_F16(d0,d1,d2,d3,a0,a1,a2,a3,b0,b1)                                    \
    asm volatile("mma.sync.aligned.m16n8k16.row.col.f32.f16.f16.f32 "             \
                 "{%0,%1,%2,%3},{%4,%5,%6,%7},{%8,%9},{%0,%1,%2,%3};"             \
                 : "+f"(d0), "+f"(d1), "+f"(d2), "+f"(d3)                         \
                 : "r"(a0), "r"(a1), "r"(a2), "r"(a3), "r"(b0), "r"(b1))

#define LDSM_X4(r0,r1,r2,r3,addr)                                                 \
    asm volatile("ldmatrix.sync.aligned.m8n8.x4.shared.b16 "                      \
                 "{%0,%1,%2,%3}, [%4];"                                           \
                 : "=r"(r0), "=r"(r1), "=r"(r2), "=r"(r3) : "r"(addr))

#define LDSM_X4_TRANS(r0,r1,r2,r3,addr)                                           \
    asm volatile("ldmatrix.sync.aligned.m8n8.x4.trans.shared.b16 "                \
                 "{%0,%1,%2,%3}, [%4];"                                           \
                 : "=r"(r0), "=r"(r1), "=r"(r2), "=r"(r3) : "r"(addr))

// ---------------------------------------------------------------------------
// fp16 tensor-core GEMM NT: C[M,N] = A[M,K] * W[N,K]^T  (fp32 in/out, fp16
// mma with fp32 accum — same 11-bit mantissa as tf32).
// Block tile 128x128, BK=16, double-buffered smem, 256 thr = 8 warps (2x4),
// warp tile 64x32, m16n8k16 + ldmatrix.x4 (stride 24 halves = conflict-free).
// MODE 0: C row-major.  MODE 1: scatter into head layout [b,h,t,d], with
// optional fused RoPE (each accumulator float2 = one interleaved pair).
// ---------------------------------------------------------------------------
#define GST 24          // halves per smem row (16 data + 8 pad)
#define NKT (DD/16)     // 64 k-tiles

template<int MODE>
__device__ __forceinline__
void hgemm_body(const float* __restrict__ A, const float* __restrict__ W,
                float* __restrict__ C, int K, int N,
                int rowBase, int colBase, int doRope)
{
    __shared__ __half As[2][128*GST];
    __shared__ __half Bs[2][128*GST];

    const int tid  = threadIdx.x;
    const int lane = tid & 31;
    const int warp = tid >> 5;
    const int grp  = lane >> 2;
    const int qk   = lane & 3;
    const int warpM = (warp & 1) * 64;
    const int warpN = (warp >> 1) * 32;

    float acc[4][4][4];
#pragma unroll
    for (int mt = 0; mt < 4; ++mt)
#pragma unroll
        for (int nt = 0; nt < 4; ++nt)
#pragma unroll
            for (int r = 0; r < 4; ++r) acc[mt][nt][r] = 0.f;

    // loader: row = tid>>1 (0..127), col = (tid&1)*8 floats
    const int ldRow = tid >> 1;
    const int ldC   = (tid & 1) * 8;
    const float* Ap = A + (size_t)(rowBase + ldRow) * K + ldC;
    const float* Wp = W + (size_t)(colBase + ldRow) * K + ldC;
    const int sOff = ldRow * GST + ldC;          // half index

    // ldmatrix source offsets (bytes) within a buffer
    const unsigned aSm = (unsigned)__cvta_generic_to_shared(&As[0][0]);
    const unsigned bSm = (unsigned)__cvta_generic_to_shared(&Bs[0][0]);
    const unsigned bufStep = 128*GST*2;          // bytes per buffer
    const int lmRow = lane & 15;
    const int lmCol = (lane >> 4) * 8;

    // ---- prologue: tile 0 ----
    {
        float4 a0 = *(const float4*)(Ap);
        float4 a1 = *(const float4*)(Ap + 4);
        float4 b0 = *(const float4*)(Wp);
        float4 b1 = *(const float4*)(Wp + 4);
        uint4 ua = make_uint4(pack_h2(a0.x,a0.y), pack_h2(a0.z,a0.w),
                              pack_h2(a1.x,a1.y), pack_h2(a1.z,a1.w));
        uint4 ub = make_uint4(pack_h2(b0.x,b0.y), pack_h2(b0.z,b0.w),
                              pack_h2(b1.x,b1.y), pack_h2(b1.z,b1.w));
        *(uint4*)&As[0][sOff] = ua;
        *(uint4*)&Bs[0][sOff] = ub;
    }
    __syncthreads();

    int buf = 0;
    for (int t = 0; t < NKT; ++t) {
        // prefetch next tile (gmem -> regs)
        float4 pa0, pa1, pb0, pb1;
        if (t + 1 < NKT) {
            const int k0 = (t + 1) * 16;
            pa0 = *(const float4*)(Ap + k0);
            pa1 = *(const float4*)(Ap + k0 + 4);
            pb0 = *(const float4*)(Wp + k0);
            pb1 = *(const float4*)(Wp + k0 + 4);
        }

        // compute on current buffer
        const unsigned ab = aSm + buf * bufStep;
        const unsigned bb = bSm + buf * bufStep;
        unsigned a[4][4];
#pragma unroll
        for (int mt = 0; mt < 4; ++mt) {
            const unsigned addr = ab + ((warpM + mt*16 + lmRow)*GST + lmCol)*2;
            LDSM_X4(a[mt][0], a[mt][1], a[mt][2], a[mt][3], addr);
        }
        unsigned b0[4], b1[4];
#pragma unroll
        for (int nc = 0; nc < 2; ++nc) {
            unsigned r0, r1, r2, r3;
            const unsigned addr = bb + ((warpN + nc*16 + lmRow)*GST + lmCol)*2;
            LDSM_X4(r0, r1, r2, r3, addr);
            b0[2*nc] = r0; b0[2*nc+1] = r1;
            b1[2*nc] = r2; b1[2*nc+1] = r3;
        }
#pragma unroll
        for (int mt = 0; mt < 4; ++mt)
#pragma unroll
            for (int nt = 0; nt < 4; ++nt)
                MMA_F16(acc[mt][nt][0], acc[mt][nt][1],
                        acc[mt][nt][2], acc[mt][nt][3],
                        a[mt][0], a[mt][1], a[mt][2], a[mt][3],
                        b0[nt], b1[nt]);

        if (t + 1 < NKT) {
            const int nb = buf ^ 1;
            uint4 ua = make_uint4(pack_h2(pa0.x,pa0.y), pack_h2(pa0.z,pa0.w),
                                  pack_h2(pa1.x,pa1.y), pack_h2(pa1.z,pa1.w));
            uint4 ub = make_uint4(pack_h2(pb0.x,pb0.y), pack_h2(pb0.z,pb0.w),
                                  pack_h2(pb1.x,pb1.y), pack_h2(pb1.z,pb1.w));
            *(uint4*)&As[nb][sOff] = ua;
            *(uint4*)&Bs[nb][sOff] = ub;
            __syncthreads();
        }
        buf ^= 1;
    }

    // ---- epilogue ----
#pragma unroll
    for (int mt = 0; mt < 4; ++mt) {
#pragma unroll
        for (int nt = 0; nt < 4; ++nt) {
            const int r0 = rowBase + warpM + mt*16 + grp;
            const int c  = colBase + warpN + nt*8 + 2*qk;
            float2 v0 = make_float2(acc[mt][nt][0], acc[mt][nt][1]);
            float2 v1 = make_float2(acc[mt][nt][2], acc[mt][nt][3]);
            if (MODE == 0) {
                *(float2*)&C[(size_t)r0 * N + c]     = v0;
                *(float2*)&C[(size_t)(r0+8) * N + c] = v1;
            } else {
                const int h = c / DH, d = c % DH;
                const int b0 = r0 / TT, t0 = r0 % TT;
                const int b1 = (r0+8) / TT, t1 = (r0+8) % TT;
                if (doRope) {
                    const int pair = d >> 1;
                    const float freq = powf(10000.0f, -(float)pair * (1.0f/32.0f));
                    float s0, c0, s1, c1;
                    sincosf((float)t0 * freq, &s0, &c0);
                    sincosf((float)t1 * freq, &s1, &c1);
                    v0 = make_float2(c0*v0.x - s0*v0.y, s0*v0.x + c0*v0.y);
                    v1 = make_float2(c1*v1.x - s1*v1.y, s1*v1.x + c1*v1.y);
                }
                *(float2*)&C[(((size_t)(b0*NH + h))*TT + t0)*DH + d] = v0;
                *(float2*)&C[(((size_t)(b1*NH + h))*TT + t1)*DH + d] = v1;
            }
        }
    }
}

// QKV fused: grid.z selects projection; head-layout scatter; RoPE on Q,K.
__global__ __launch_bounds__(256, 2)
void hgemm_qkv(const float* __restrict__ h,
               const float* __restrict__ wq, const float* __restrict__ wk,
               const float* __restrict__ wv,
               float* __restrict__ Qo, float* __restrict__ Ko, float* __restrict__ Vo)
{
    const float* W = (blockIdx.z == 0) ? wq : (blockIdx.z == 1) ? wk : wv;
    float*       C = (blockIdx.z == 0) ? Qo : (blockIdx.z == 1) ? Ko : Vo;
    hgemm_body<1>(h, W, C, DD, DD, blockIdx.y * 128, blockIdx.x * 128,
                  blockIdx.z < 2);
}

__global__ __launch_bounds__(256, 2)
void hgemm_out(const float* __restrict__ A, const float* __restrict__ W,
               float* __restrict__ C)
{
    hgemm_body<0>(A, W, C, DD, DD, blockIdx.y * 128, blockIdx.x * 128, 0);
}

// ---------------------------------------------------------------------------
// Tensor-core causal flash attention (unchanged from R4 winner).
// QK^T: tf32 m16n8k8 (Q in registers, K tf32 smem stride 68, conflict-free).
// PV:   fp16 m16n8k16 — P packed in-register, V fp16 via ldmatrix.x4.trans.
// ---------------------------------------------------------------------------
#define KST  68
#define VSTH 72   // halves per V row
#define VSTU 36   // uints per V row

__global__ __launch_bounds__(256, 2)
void flash_tc(const float* __restrict__ Q, const float* __restrict__ K,
              const float* __restrict__ V, float* __restrict__ Ao)
{
    __shared__ unsigned Ks[64*KST];
    __shared__ unsigned Vh[64*VSTU];

    const int tid  = threadIdx.x;
    const int lane = tid & 31;
    const int warp = tid >> 5;
    const int grp  = lane >> 2;
    const int qk   = lane & 3;
    const int qtile = gridDim.x - 1 - blockIdx.x;   // heavy tiles first
    const int bh    = blockIdx.y;
    const int qbase = qtile * 128;
    const int warpRow = warp * 16;

    const float* Qp = Q + (size_t)bh * TT * DH;
    const float* Kp = K + (size_t)bh * TT * DH;
    const float* Vp = V + (size_t)bh * TT * DH;

    const unsigned vbase = (unsigned)__cvta_generic_to_shared(Vh);
    const int lm_row = lane & 15;
    const int lm_col = (lane >> 4) * 8;

    const int qi0 = qbase + warpRow + grp;
    const int qi1 = qi0 + 8;
    unsigned qa0[16], qa1[16];
    {
        const float* q0 = Qp + (size_t)qi0 * DH + qk;
        const float* q1 = Qp + (size_t)qi1 * DH + qk;
#pragma unroll
        for (int j = 0; j < 16; ++j) {
            qa0[j] = f2tf32(q0[4*j]);
            qa1[j] = f2tf32(q1[4*j]);
        }
    }

    float m0 = -1e30f, m1 = -1e30f, l0 = 0.f, l1 = 0.f;
    float oa[8][4];
#pragma unroll
    for (int nt = 0; nt < 8; ++nt)
#pragma unroll
        for (int r = 0; r < 4; ++r) oa[nt][r] = 0.f;

    const int ldRow = tid >> 2;
    const int ldD0  = (tid & 3) * 16;

    const int lastKt = 2*qtile + 1;
    for (int kt = 0; kt <= lastKt; ++kt) {
        const int kbase = kt * 64;
        __syncthreads();
        {
            const float4* kg = (const float4*)&Kp[(size_t)(kbase + ldRow)*DH + ldD0];
            const float4* vg = (const float4*)&Vp[(size_t)(kbase + ldRow)*DH + ldD0];
            unsigned* kd = &Ks[ldRow*KST + ldD0];
            unsigned* vd = &Vh[ldRow*VSTU + (ldD0 >> 1)];
#pragma unroll
            for (int c = 0; c < 4; ++c) {
                float4 kv = kg[c];
                kd[4*c+0] = f2tf32(kv.x); kd[4*c+1] = f2tf32(kv.y);
                kd[4*c+2] = f2tf32(kv.z); kd[4*c+3] = f2tf32(kv.w);
                float4 vv = vg[c];
                vd[2*c+0] = pack_h2(vv.x, vv.y);
                vd[2*c+1] = pack_h2(vv.z, vv.w);
            }
        }
        __syncthreads();

        float sa[8][4];
#pragma unroll
        for (int nt = 0; nt < 8; ++nt)
#pragma unroll
            for (int r = 0; r < 4; ++r) sa[nt][r] = 0.f;

#pragma unroll
        for (int ks = 0; ks < 8; ++ks) {
            const unsigned a0 = qa0[2*ks], a2 = qa0[2*ks+1];
            const unsigned a1 = qa1[2*ks], a3 = qa1[2*ks+1];
#pragma unroll
            for (int nt = 0; nt < 8; ++nt) {
                const unsigned* kb = &Ks[(nt*8 + grp)*KST + ks*8 + qk];
                MMA_TF32(sa[nt][0], sa[nt][1], sa[nt][2], sa[nt][3],
                         a0, a1, a2, a3, kb[0], kb[4]);
            }
        }

        const float sc = 0.125f;
        if (kbase + 63 > qbase) {
#pragma unroll
            for (int nt = 0; nt < 8; ++nt) {
                const int c0 = kbase + nt*8 + 2*qk;
                const int c1 = c0 + 1;
                sa[nt][0] = (c0 <= qi0) ? sa[nt][0]*sc : -1e30f;
                sa[nt][1] = (c1 <= qi0) ? sa[nt][1]*sc : -1e30f;
                sa[nt][2] = (c0 <= qi1) ? sa[nt][2]*sc : -1e30f;
                sa[nt][3] = (c1 <= qi1) ? sa[nt][3]*sc : -1e30f;
            }
        } else {
#pragma unroll
            for (int nt = 0; nt < 8; ++nt)
#pragma unroll
                for (int r = 0; r < 4; ++r) sa[nt][r] *= sc;
        }

        float mx0 = sa[0][0], mx1 = sa[0][2];
#pragma unroll
        for (int nt = 0; nt < 8; ++nt) {
            mx0 = fmaxf(mx0, fmaxf(sa[nt][0], sa[nt][1]));
            mx1 = fmaxf(mx1, fmaxf(sa[nt][2], sa[nt][3]));
        }
        mx0 = fmaxf(mx0, __shfl_xor_sync(0xffffffffu, mx0, 1));
        mx0 = fmaxf(mx0, __shfl_xor_sync(0xffffffffu, mx0, 2));
        mx1 = fmaxf(mx1, __shfl_xor_sync(0xffffffffu, mx1, 1));
        mx1 = fmaxf(mx1, __shfl_xor_sync(0xffffffffu, mx1, 2));

        const float nm0 = fmaxf(m0, mx0);
        const float nm1 = fmaxf(m1, mx1);
        const float al0 = __expf(m0 - nm0);
        const float al1 = __expf(m1 - nm1);
        m0 = nm0; m1 = nm1;

        float rs0 = 0.f, rs1 = 0.f;
#pragma unroll
        for (int nt = 0; nt < 8; ++nt) {
            sa[nt][0] = __expf(sa[nt][0] - nm0);
            sa[nt][1] = __expf(sa[nt][1] - nm0);
            sa[nt][2] = __expf(sa[nt][2] - nm1);
            sa[nt][3] = __expf(sa[nt][3] - nm1);
            rs0 += sa[nt][0] + sa[nt][1];
            rs1 += sa[nt][2] + sa[nt][3];
        }
        rs0 += __shfl_xor_sync(0xffffffffu, rs0, 1);
        rs0 += __shfl_xor_sync(0xffffffffu, rs0, 2);
        rs1 += __shfl_xor_sync(0xffffffffu, rs1, 1);
        rs1 += __shfl_xor_sync(0xffffffffu, rs1, 2);
        l0 = l0*al0 + rs0;
        l1 = l1*al1 + rs1;

#pragma unroll
        for (int nt = 0; nt < 8; ++nt) {
            oa[nt][0] *= al0; oa[nt][1] *= al0;
            oa[nt][2] *= al1; oa[nt][3] *= al1;
        }

#pragma unroll
        for (int kc = 0; kc < 4; ++kc) {
            const unsigned a0 = pack_h2(sa[2*kc  ][0], sa[2*kc  ][1]);
            const unsigned a1 = pack_h2(sa[2*kc  ][2], sa[2*kc  ][3]);
            const unsigned a2 = pack_h2(sa[2*kc+1][0], sa[2*kc+1][1]);
            const unsigned a3 = pack_h2(sa[2*kc+1][2], sa[2*kc+1][3]);
            const unsigned raddr = vbase +
                (((kc*16 + lm_row) * VSTH) + lm_col) * 2;
#pragma unroll
            for (int np = 0; np < 4; ++np) {
                unsigned b0, b1, b2, b3;
                LDSM_X4_TRANS(b0, b1, b2, b3, raddr + np*32);
                MMA_F16(oa[2*np  ][0], oa[2*np  ][1], oa[2*np  ][2], oa[2*np  ][3],
                        a0, a1, a2, a3, b0, b1);
                MMA_F16(oa[2*np+1][0], oa[2*np+1][1], oa[2*np+1][2], oa[2*np+1][3],
                        a0, a1, a2, a3, b2, b3);
            }
        }
    }

    const int b = bh / NH, hh = bh % NH;
    const float inv0 = 1.f / l0;
    const float inv1 = 1.f / l1;
    float* d0 = &Ao[((size_t)(b*TT + qi0))*DD + hh*DH];
    float* d1 = &Ao[((size_t)(b*TT + qi1))*DD + hh*DH];
#pragma unroll
    for (int nt = 0; nt < 8; ++nt) {
        const int c = nt*8 + 2*qk;
        *(float2*)&d0[c] = make_float2(oa[nt][0]*inv0, oa[nt][1]*inv0);
        *(float2*)&d1[c] = make_float2(oa[nt][2]*inv1, oa[nt][3]*inv1);
    }
}

// ---------------------------------------------------------------------------
extern "C" void kernel_launch(void* const* d_in, const int* in_sizes, int n_in,
                              void* d_out, int out_size)
{
    const float* h  = (const float*)d_in[0];
    const float* wq = (const float*)d_in[1];
    const float* wk = (const float*)d_in[2];
    const float* wv = (const float*)d_in[3];
    const float* wo = (const float*)d_in[4];
    float* out = (float*)d_out;
    (void)in_sizes; (void)n_in; (void)out_size;

    float *pQ, *pK, *pV, *pA;
    cudaGetSymbolAddress((void**)&pQ, g_Q);
    cudaGetSymbolAddress((void**)&pK, g_K);
    cudaGetSymbolAddress((void**)&pV, g_V);
    cudaGetSymbolAddress((void**)&pA, g_A);

    hgemm_qkv<<<dim3(DD/128, BT/128, 3), 256>>>(h, wq, wk, wv, pQ, pK, pV);

    flash_tc<<<dim3(TT/128, BB*NH), 256>>>(pQ, pK, pV, pA);

    hgemm_out<<<dim3(DD/128, BT/128), 256>>>(pA, wo, out);
}

// round 8
// speedup vs baseline: 7.7558x; 1.8225x over previous
#include <cuda_runtime.h>
#include <cuda_fp16.h>
#include <math.h>

#define BB 2
#define TT 2048
#define DD 1024
#define NH 16
#define DH 64
#define BT (BB*TT)

// fp16 scratch (allocation-free rule: __device__ globals)
__device__ __half g_h16[BT*DD];          // h converted
__device__ __half g_w16[4][DD*DD];       // wq, wk, wv, wo converted
__device__ __half g_Qh[BB*NH*TT*DH];     // [b,h,t,d] RoPE'd
__device__ __half g_Kh[BB*NH*TT*DH];
__device__ __half g_Vh[BB*NH*TT*DH];
__device__ __half g_A16[BT*DD];          // attention out [b,t,h*dh]

__device__ __forceinline__ unsigned pack_h2(float x, float y) {
    unsigned r;
    asm("cvt.rn.f16x2.f32 %0, %1, %2;" : "=r"(r) : "f"(y), "f"(x));
    return r;
}

#define MMA_F16(d0,d1,d2,d3,a0,a1,a2,a3,b0,b1)                                    \
    asm volatile("mma.sync.aligned.m16n8k16.row.col.f32.f16.f16.f32 "             \
                 "{%0,%1,%2,%3},{%4,%5,%6,%7},{%8,%9},{%0,%1,%2,%3};"             \
                 : "+f"(d0), "+f"(d1), "+f"(d2), "+f"(d3)                         \
                 : "r"(a0), "r"(a1), "r"(a2), "r"(a3), "r"(b0), "r"(b1))

#define LDSM_X4(r0,r1,r2,r3,addr)                                                 \
    asm volatile("ldmatrix.sync.aligned.m8n8.x4.shared.b16 "                      \
                 "{%0,%1,%2,%3}, [%4];"                                           \
                 : "=r"(r0), "=r"(r1), "=r"(r2), "=r"(r3) : "r"(addr))

#define LDSM_X4_TRANS(r0,r1,r2,r3,addr)                                           \
    asm volatile("ldmatrix.sync.aligned.m8n8.x4.trans.shared.b16 "                \
                 "{%0,%1,%2,%3}, [%4];"                                           \
                 : "=r"(r0), "=r"(r1), "=r"(r2), "=r"(r3) : "r"(addr))

#define CP_ASYNC16(dst, src)                                                      \
    asm volatile("cp.async.cg.shared.global [%0], [%1], 16;" :: "r"(dst), "l"(src))
#define CP_COMMIT() asm volatile("cp.async.commit_group;")
#define CP_WAIT0()  asm volatile("cp.async.wait_group 0;")
#define CP_WAIT1()  asm volatile("cp.async.wait_group 1;")

// ---------------------------------------------------------------------------
// fp32 -> fp16 conversion: segment 0 = h (4M), 1-4 = weights (1M each)
// ---------------------------------------------------------------------------
__global__ void cvt5(const float* __restrict__ h,  const float* __restrict__ wq,
                     const float* __restrict__ wk, const float* __restrict__ wv,
                     const float* __restrict__ wo)
{
    const float* src; __half* dst; int n;
    switch (blockIdx.y) {
        case 0: src = h;  dst = g_h16;     n = BT*DD; break;
        case 1: src = wq; dst = g_w16[0];  n = DD*DD; break;
        case 2: src = wk; dst = g_w16[1];  n = DD*DD; break;
        case 3: src = wv; dst = g_w16[2];  n = DD*DD; break;
        default:src = wo; dst = g_w16[3];  n = DD*DD; break;
    }
    const int idx = (blockIdx.x * blockDim.x + threadIdx.x) * 8;
    if (idx >= n) return;
    float4 v0 = *(const float4*)(src + idx);
    float4 v1 = *(const float4*)(src + idx + 4);
    uint4 u = make_uint4(pack_h2(v0.x, v0.y), pack_h2(v0.z, v0.w),
                         pack_h2(v1.x, v1.y), pack_h2(v1.z, v1.w));
    *(uint4*)&dst[idx] = u;
}

// ---------------------------------------------------------------------------
// fp16 cp.async GEMM NT: C = A[M,K] * W[N,K]^T, fp32 accum.
// 128x128 tile, BK=32, 3-stage cp.async pipeline, SW128-swizzled smem,
// 256 thr = 8 warps (2x4), warp tile 64x32, ldmatrix.x4 (conflict-free).
// MODE 0: fp32 C row-major.  MODE 1: fp16 C head layout + optional RoPE.
// ---------------------------------------------------------------------------
#define BK16  32
#define NKT16 (DD/BK16)     // 32
#define TILEB 8192          // bytes per operand tile (128 rows x 64B)

// byte offset within 8KB tile: 128 rows x 64B, SW128 over row pairs
__device__ __forceinline__ unsigned swz(int row, int chunk) {
    return ((row >> 1) << 7) |
           ((((((row & 1) << 2) | chunk) ^ ((row >> 1) & 7))) << 4);
}

template<int MODE>
__device__ __forceinline__
void hgemm16_body(const __half* __restrict__ A, const __half* __restrict__ W,
                  float* __restrict__ Cf, __half* __restrict__ Ch,
                  int rowBase, int colBase, int doRope)
{
    extern __shared__ __half dsm[];
    const unsigned aSm = (unsigned)__cvta_generic_to_shared(dsm);
    const unsigned bSm = aSm + 3 * TILEB;

    const int tid  = threadIdx.x;
    const int lane = tid & 31;
    const int warp = tid >> 5;
    const int grp  = lane >> 2;
    const int qk   = lane & 3;
    const int warpM = (warp & 1) * 64;
    const int warpN = (warp >> 1) * 32;
    const int lmRow = lane & 15;
    const int lmSel = lane >> 4;

    float acc[4][4][4];
#pragma unroll
    for (int mt = 0; mt < 4; ++mt)
#pragma unroll
        for (int nt = 0; nt < 4; ++nt)
#pragma unroll
            for (int r = 0; r < 4; ++r) acc[mt][nt][r] = 0.f;

    // loader: thread handles chunks (r0,c0) and (r0+64,c0) for A and W
    const int r0 = tid >> 2;        // 0..63
    const int c0 = tid & 3;         // 0..3
    const __half* Ab = A + (size_t)(rowBase + r0) * DD + c0 * 8;
    const __half* Wb = W + (size_t)(colBase + r0) * DD + c0 * 8;
    const unsigned da0 = swz(r0, c0),      da1 = swz(r0 + 64, c0);

#define G_ISSUE(t, s)                                                         \
    do {                                                                      \
        const __half* as_ = Ab + (t) * BK16;                                  \
        const __half* ws_ = Wb + (t) * BK16;                                  \
        CP_ASYNC16(aSm + (s) * TILEB + da0, as_);                             \
        CP_ASYNC16(aSm + (s) * TILEB + da1, as_ + (size_t)64 * DD);           \
        CP_ASYNC16(bSm + (s) * TILEB + da0, ws_);                             \
        CP_ASYNC16(bSm + (s) * TILEB + da1, ws_ + (size_t)64 * DD);           \
        CP_COMMIT();                                                          \
    } while (0)

    G_ISSUE(0, 0);
    G_ISSUE(1, 1);

    int buf = 0;
    for (int t = 0; t < NKT16; ++t) {
        if (t + 1 < NKT16) { CP_WAIT1(); } else { CP_WAIT0(); }
        __syncthreads();
        if (t + 2 < NKT16) {
            const int s = (t + 2) % 3;
            G_ISSUE(t + 2, s);
        }

        const unsigned ab = aSm + buf * TILEB;
        const unsigned bb = bSm + buf * TILEB;
#pragma unroll
        for (int kc = 0; kc < 2; ++kc) {
            const int ch = kc * 2 + lmSel;
            unsigned a[4][4];
#pragma unroll
            for (int mt = 0; mt < 4; ++mt)
                LDSM_X4(a[mt][0], a[mt][1], a[mt][2], a[mt][3],
                        ab + swz(warpM + mt*16 + lmRow, ch));
            unsigned bl[4], bh[4];
#pragma unroll
            for (int nc = 0; nc < 2; ++nc) {
                unsigned x0, x1, x2, x3;
                LDSM_X4(x0, x1, x2, x3, bb + swz(warpN + nc*16 + lmRow, ch));
                bl[2*nc] = x0; bl[2*nc+1] = x1;
                bh[2*nc] = x2; bh[2*nc+1] = x3;
            }
#pragma unroll
            for (int mt = 0; mt < 4; ++mt)
#pragma unroll
                for (int nt = 0; nt < 4; ++nt)
                    MMA_F16(acc[mt][nt][0], acc[mt][nt][1],
                            acc[mt][nt][2], acc[mt][nt][3],
                            a[mt][0], a[mt][1], a[mt][2], a[mt][3],
                            bl[nt], bh[nt]);
        }
        buf = (buf + 1) % 3;
    }
#undef G_ISSUE

    // ---- epilogue ----
#pragma unroll
    for (int mt = 0; mt < 4; ++mt) {
#pragma unroll
        for (int nt = 0; nt < 4; ++nt) {
            const int rr = rowBase + warpM + mt*16 + grp;
            const int c  = colBase + warpN + nt*8 + 2*qk;
            float2 v0 = make_float2(acc[mt][nt][0], acc[mt][nt][1]);
            float2 v1 = make_float2(acc[mt][nt][2], acc[mt][nt][3]);
            if (MODE == 0) {
                *(float2*)&Cf[(size_t)rr * DD + c]       = v0;
                *(float2*)&Cf[(size_t)(rr+8) * DD + c]   = v1;
            } else {
                const int hh = c / DH, d = c % DH;
                const int b0 = rr / TT, t0 = rr % TT;
                const int b1 = (rr+8) / TT, t1 = (rr+8) % TT;
                if (doRope) {
                    const int pair = d >> 1;
                    const float freq = powf(10000.0f, -(float)pair * (1.0f/32.0f));
                    float s0, cc0, s1, cc1;
                    sincosf((float)t0 * freq, &s0, &cc0);
                    sincosf((float)t1 * freq, &s1, &cc1);
                    v0 = make_float2(cc0*v0.x - s0*v0.y, s0*v0.x + cc0*v0.y);
                    v1 = make_float2(cc1*v1.x - s1*v1.y, s1*v1.x + cc1*v1.y);
                }
                *(unsigned*)&Ch[(((size_t)(b0*NH + hh))*TT + t0)*DH + d] =
                    pack_h2(v0.x, v0.y);
                *(unsigned*)&Ch[(((size_t)(b1*NH + hh))*TT + t1)*DH + d] =
                    pack_h2(v1.x, v1.y);
            }
        }
    }
}

__global__ __launch_bounds__(256, 2)
void hgemm16_qkv()
{
    const int z = blockIdx.z;
    const __half* W = g_w16[z];
    __half* C = (z == 0) ? g_Qh : (z == 1) ? g_Kh : g_Vh;
    hgemm16_body<1>(g_h16, W, nullptr, C,
                    blockIdx.y * 128, blockIdx.x * 128, z < 2);
}

__global__ __launch_bounds__(256, 2)
void hgemm16_out(float* __restrict__ out)
{
    hgemm16_body<0>(g_A16, g_w16[3], out, nullptr,
                    blockIdx.y * 128, blockIdx.x * 128, 0);
}

// ---------------------------------------------------------------------------
// fp16 tensor-core causal flash attention.
// QK^T: fp16 m16n8k16 (Q frags straight from gmem; K via cp.async + ldmatrix).
// PV:   fp16 m16n8k16, P packed in-register, V via ldmatrix.x4.trans.
// K/V double-buffered cp.async (load of tile t+1 overlaps compute of t).
// BM=128 (8 warps x 16 rows), BN=64, dh=64, 256 threads.
// Smem: sK[2][64][72] + sV[2][64][72] halves = 36864 B.
// ---------------------------------------------------------------------------
#define FKST  72                      // halves per K/V smem row (64 + 8 pad)
#define FTILE (64*FKST*2)             // 9216 bytes per tensor per stage

__global__ __launch_bounds__(256, 2)
void flash16()
{
    __shared__ __half sK[2*64*FKST];
    __shared__ __half sV[2*64*FKST];
    const unsigned kSm = (unsigned)__cvta_generic_to_shared(sK);
    const unsigned vSm = (unsigned)__cvta_generic_to_shared(sV);

    const int tid  = threadIdx.x;
    const int lane = tid & 31;
    const int warp = tid >> 5;
    const int grp  = lane >> 2;
    const int qk   = lane & 3;
    const int qtile = gridDim.x - 1 - blockIdx.x;   // heavy tiles first
    const int bh    = blockIdx.y;
    const int qbase = qtile * 128;

    const __half* Qp = g_Qh + (size_t)bh * TT * DH;
    const __half* Kp = g_Kh + (size_t)bh * TT * DH;
    const __half* Vp = g_Vh + (size_t)bh * TT * DH;

    const int lmRow = lane & 15;
    const int lmSel = lane >> 4;

    // ---- Q fragments (fp16 m16n8k16 A layout), loaded once from gmem ----
    const int qi0 = qbase + warp*16 + grp;
    const int qi1 = qi0 + 8;
    unsigned qa[4][4];
    {
        const __half* q0 = Qp + (size_t)qi0 * DH;
        const __half* q1 = Qp + (size_t)qi1 * DH;
#pragma unroll
        for (int kc = 0; kc < 4; ++kc) {
            qa[kc][0] = *(const unsigned*)(q0 + kc*16 + 2*qk);
            qa[kc][1] = *(const unsigned*)(q1 + kc*16 + 2*qk);
            qa[kc][2] = *(const unsigned*)(q0 + kc*16 + 8 + 2*qk);
            qa[kc][3] = *(const unsigned*)(q1 + kc*16 + 8 + 2*qk);
        }
    }

    float m0 = -1e30f, m1 = -1e30f, l0 = 0.f, l1 = 0.f;
    float oa[8][4];
#pragma unroll
    for (int nt = 0; nt < 8; ++nt)
#pragma unroll
        for (int r = 0; r < 4; ++r) oa[nt][r] = 0.f;

    // cp.async loader: thread -> rows fr, fr+32, chunk fc (16B)
    const int fr = tid >> 3;          // 0..31
    const int fc = tid & 7;           // 0..7
    const unsigned dk0 = (fr*FKST + fc*8) * 2;
    const unsigned dk1 = ((fr+32)*FKST + fc*8) * 2;

#define F_ISSUE(kt, s)                                                        \
    do {                                                                      \
        const __half* ks_ = Kp + (size_t)((kt)*64 + fr) * DH + fc*8;          \
        const __half* vs_ = Vp + (size_t)((kt)*64 + fr) * DH + fc*8;          \
        CP_ASYNC16(kSm + (s)*FTILE + dk0, ks_);                               \
        CP_ASYNC16(kSm + (s)*FTILE + dk1, ks_ + (size_t)32*DH);               \
        CP_ASYNC16(vSm + (s)*FTILE + dk0, vs_);                               \
        CP_ASYNC16(vSm + (s)*FTILE + dk1, vs_ + (size_t)32*DH);               \
        CP_COMMIT();                                                          \
    } while (0)

    F_ISSUE(0, 0);

    const int lastKt = 2*qtile + 1;
    for (int kt = 0; kt <= lastKt; ++kt) {
        const int kbase = kt * 64;
        const int s = kt & 1;
        CP_WAIT0();
        __syncthreads();
        if (kt < lastKt) F_ISSUE(kt + 1, (kt + 1) & 1);

        // ---- S = Q K^T (fp16) ----
        float sa[8][4];
#pragma unroll
        for (int nt = 0; nt < 8; ++nt)
#pragma unroll
            for (int r = 0; r < 4; ++r) sa[nt][r] = 0.f;

#pragma unroll
        for (int kc = 0; kc < 4; ++kc) {
#pragma unroll
            for (int nc = 0; nc < 4; ++nc) {
                unsigned x0, x1, x2, x3;
                const unsigned addr = kSm + s*FTILE +
                    ((nc*16 + lmRow)*FKST + (kc*2 + lmSel)*8) * 2;
                LDSM_X4(x0, x1, x2, x3, addr);
                MMA_F16(sa[2*nc  ][0], sa[2*nc  ][1], sa[2*nc  ][2], sa[2*nc  ][3],
                        qa[kc][0], qa[kc][1], qa[kc][2], qa[kc][3], x0, x2);
                MMA_F16(sa[2*nc+1][0], sa[2*nc+1][1], sa[2*nc+1][2], sa[2*nc+1][3],
                        qa[kc][0], qa[kc][1], qa[kc][2], qa[kc][3], x1, x3);
            }
        }

        // ---- scale + causal mask ----
        const float sc = 0.125f;   // 1/sqrt(64)
        if (kbase + 63 > qbase) {
#pragma unroll
            for (int nt = 0; nt < 8; ++nt) {
                const int c0 = kbase + nt*8 + 2*qk;
                const int c1 = c0 + 1;
                sa[nt][0] = (c0 <= qi0) ? sa[nt][0]*sc : -1e30f;
                sa[nt][1] = (c1 <= qi0) ? sa[nt][1]*sc : -1e30f;
                sa[nt][2] = (c0 <= qi1) ? sa[nt][2]*sc : -1e30f;
                sa[nt][3] = (c1 <= qi1) ? sa[nt][3]*sc : -1e30f;
            }
        } else {
#pragma unroll
            for (int nt = 0; nt < 8; ++nt)
#pragma unroll
                for (int r = 0; r < 4; ++r) sa[nt][r] *= sc;
        }

        // ---- online softmax ----
        float mx0 = sa[0][0], mx1 = sa[0][2];
#pragma unroll
        for (int nt = 0; nt < 8; ++nt) {
            mx0 = fmaxf(mx0, fmaxf(sa[nt][0], sa[nt][1]));
            mx1 = fmaxf(mx1, fmaxf(sa[nt][2], sa[nt][3]));
        }
        mx0 = fmaxf(mx0, __shfl_xor_sync(0xffffffffu, mx0, 1));
        mx0 = fmaxf(mx0, __shfl_xor_sync(0xffffffffu, mx0, 2));
        mx1 = fmaxf(mx1, __shfl_xor_sync(0xffffffffu, mx1, 1));
        mx1 = fmaxf(mx1, __shfl_xor_sync(0xffffffffu, mx1, 2));

        const float nm0 = fmaxf(m0, mx0);
        const float nm1 = fmaxf(m1, mx1);
        const float al0 = __expf(m0 - nm0);
        const float al1 = __expf(m1 - nm1);
        m0 = nm0; m1 = nm1;

        float rs0 = 0.f, rs1 = 0.f;
#pragma unroll
        for (int nt = 0; nt < 8; ++nt) {
            sa[nt][0] = __expf(sa[nt][0] - nm0);
            sa[nt][1] = __expf(sa[nt][1] - nm0);
            sa[nt][2] = __expf(sa[nt][2] - nm1);
            sa[nt][3] = __expf(sa[nt][3] - nm1);
            rs0 += sa[nt][0] + sa[nt][1];
            rs1 += sa[nt][2] + sa[nt][3];
        }
        rs0 += __shfl_xor_sync(0xffffffffu, rs0, 1);
        rs0 += __shfl_xor_sync(0xffffffffu, rs0, 2);
        rs1 += __shfl_xor_sync(0xffffffffu, rs1, 1);
        rs1 += __shfl_xor_sync(0xffffffffu, rs1, 2);
        l0 = l0*al0 + rs0;
        l1 = l1*al1 + rs1;

#pragma unroll
        for (int nt = 0; nt < 8; ++nt) {
            oa[nt][0] *= al0; oa[nt][1] *= al0;
            oa[nt][2] *= al1; oa[nt][3] *= al1;
        }

        // ---- O += P V (fp16, P packed in-register) ----
#pragma unroll
        for (int kc = 0; kc < 4; ++kc) {
            const unsigned a0 = pack_h2(sa[2*kc  ][0], sa[2*kc  ][1]);
            const unsigned a1 = pack_h2(sa[2*kc  ][2], sa[2*kc  ][3]);
            const unsigned a2 = pack_h2(sa[2*kc+1][0], sa[2*kc+1][1]);
            const unsigned a3 = pack_h2(sa[2*kc+1][2], sa[2*kc+1][3]);
            const unsigned raddr = vSm + s*FTILE +
                (((kc*16 + lmRow) * FKST) + lmSel*8) * 2;
#pragma unroll
            for (int np = 0; np < 4; ++np) {
                unsigned b0, b1, b2, b3;
                LDSM_X4_TRANS(b0, b1, b2, b3, raddr + np*32);
                MMA_F16(oa[2*np  ][0], oa[2*np  ][1], oa[2*np  ][2], oa[2*np  ][3],
                        a0, a1, a2, a3, b0, b1);
                MMA_F16(oa[2*np+1][0], oa[2*np+1][1], oa[2*np+1][2], oa[2*np+1][3],
                        a0, a1, a2, a3, b2, b3);
            }
        }
    }
#undef F_ISSUE

    // ---- epilogue: normalize, write fp16 to [b, t, h*dh] ----
    const int b = bh / NH, hh = bh % NH;
    const float inv0 = 1.f / l0;
    const float inv1 = 1.f / l1;
    __half* d0 = g_A16 + ((size_t)(b*TT + qi0))*DD + hh*DH;
    __half* d1 = g_A16 + ((size_t)(b*TT + qi1))*DD + hh*DH;
#pragma unroll
    for (int nt = 0; nt < 8; ++nt) {
        const int c = nt*8 + 2*qk;
        *(unsigned*)&d0[c] = pack_h2(oa[nt][0]*inv0, oa[nt][1]*inv0);
        *(unsigned*)&d1[c] = pack_h2(oa[nt][2]*inv1, oa[nt][3]*inv1);
    }
}

// ---------------------------------------------------------------------------
extern "C" void kernel_launch(void* const* d_in, const int* in_sizes, int n_in,
                              void* d_out, int out_size)
{
    const float* h  = (const float*)d_in[0];
    const float* wq = (const float*)d_in[1];
    const float* wk = (const float*)d_in[2];
    const float* wv = (const float*)d_in[3];
    const float* wo = (const float*)d_in[4];
    float* out = (float*)d_out;
    (void)in_sizes; (void)n_in; (void)out_size;

    const int gsmem = 6 * TILEB;   // 49152 B
    static int inited = 0;
    cudaFuncSetAttribute(hgemm16_qkv, cudaFuncAttributeMaxDynamicSharedMemorySize, gsmem);
    cudaFuncSetAttribute(hgemm16_out, cudaFuncAttributeMaxDynamicSharedMemorySize, gsmem);
    (void)inited;

    cvt5<<<dim3(BT*DD/(256*8), 5), 256>>>(h, wq, wk, wv, wo);

    hgemm16_qkv<<<dim3(DD/128, BT/128, 3), 256, gsmem>>>();

    flash16<<<dim3(TT/128, BB*NH), 256>>>();

    hgemm16_out<<<dim3(DD/128, BT/128), 256, gsmem>>>(out);
}

// round 10
// speedup vs baseline: 8.2798x; 1.0676x over previous
#include <cuda_runtime.h>
#include <cuda_fp16.h>
#include <math.h>

#define BB 2
#define TT 2048
#define DD 1024
#define NH 16
#define DH 64
#define BT (BB*TT)

// fp16 scratch (allocation-free rule: __device__ globals)
__device__ __align__(16) __half g_h16[BT*DD];
__device__ __align__(16) __half g_w16[4][DD*DD];
__device__ __align__(16) __half g_Qh[BB*NH*TT*DH];
__device__ __align__(16) __half g_Kh[BB*NH*TT*DH];
__device__ __align__(16) __half g_Vh[BB*NH*TT*DH];
__device__ __align__(16) __half g_A16[BT*DD];

__device__ __forceinline__ unsigned pack_h2(float x, float y) {
    unsigned r;
    asm("cvt.rn.f16x2.f32 %0, %1, %2;" : "=r"(r) : "f"(y), "f"(x));
    return r;
}
__device__ __forceinline__ unsigned smem_u32(const void* p) {
    return (unsigned)__cvta_generic_to_shared(p);
}

#define MMA_F16(d0,d1,d2,d3,a0,a1,a2,a3,b0,b1)                                    \
    asm volatile("mma.sync.aligned.m16n8k16.row.col.f32.f16.f16.f32 "             \
                 "{%0,%1,%2,%3},{%4,%5,%6,%7},{%8,%9},{%0,%1,%2,%3};"             \
                 : "+f"(d0), "+f"(d1), "+f"(d2), "+f"(d3)                         \
                 : "r"(a0), "r"(a1), "r"(a2), "r"(a3), "r"(b0), "r"(b1))

#define LDSM_X4(r0,r1,r2,r3,addr)                                                 \
    asm volatile("ldmatrix.sync.aligned.m8n8.x4.shared.b16 "                      \
                 "{%0,%1,%2,%3}, [%4];"                                           \
                 : "=r"(r0), "=r"(r1), "=r"(r2), "=r"(r3) : "r"(addr))

#define LDSM_X4_TRANS(r0,r1,r2,r3,addr)                                           \
    asm volatile("ldmatrix.sync.aligned.m8n8.x4.trans.shared.b16 "                \
                 "{%0,%1,%2,%3}, [%4];"                                           \
                 : "=r"(r0), "=r"(r1), "=r"(r2), "=r"(r3) : "r"(addr))

#define CP_ASYNC16(dst, src)                                                      \
    asm volatile("cp.async.cg.shared.global [%0], [%1], 16;" :: "r"(dst), "l"(src))
#define CP_COMMIT() asm volatile("cp.async.commit_group;")
#define CP_WAIT0()  asm volatile("cp.async.wait_group 0;")
#define CP_WAIT1()  asm volatile("cp.async.wait_group 1;")

// ---------------------------------------------------------------------------
// fp32 -> fp16 conversion: segment 0 = h (4M), 1-4 = weights (1M each)
// ---------------------------------------------------------------------------
__global__ void cvt5(const float* __restrict__ h,  const float* __restrict__ wq,
                     const float* __restrict__ wk, const float* __restrict__ wv,
                     const float* __restrict__ wo)
{
    const float* src; __half* dst; int n;
    switch (blockIdx.y) {
        case 0: src = h;  dst = g_h16;     n = BT*DD; break;
        case 1: src = wq; dst = g_w16[0];  n = DD*DD; break;
        case 2: src = wk; dst = g_w16[1];  n = DD*DD; break;
        case 3: src = wv; dst = g_w16[2];  n = DD*DD; break;
        default:src = wo; dst = g_w16[3];  n = DD*DD; break;
    }
    const int idx = (blockIdx.x * blockDim.x + threadIdx.x) * 8;
    if (idx >= n) return;
    float4 v0 = *(const float4*)(src + idx);
    float4 v1 = *(const float4*)(src + idx + 4);
    uint4 u = make_uint4(pack_h2(v0.x, v0.y), pack_h2(v0.z, v0.w),
                         pack_h2(v1.x, v1.y), pack_h2(v1.z, v1.w));
    *(uint4*)&dst[idx] = u;
}

// ---------------------------------------------------------------------------
// fp16 cp.async GEMM NT: C = A[M,K] * W[N,K]^T, fp32 accum.
// 128x128 tile, BK=64 (full SW128 rows), 3-stage cp.async pipeline,
// 256 thr = 8 warps (2x4), warp tile 64x32, m16n8k16 + ldmatrix.x4.
// Canonical SW128 swizzle: conflict-free stores and ldmatrix reads.
// MODE 0: fp32 C row-major.  MODE 1: fp16 C head layout + optional RoPE.
// ---------------------------------------------------------------------------
#define BK64   64
#define NKT64  (DD/BK64)      // 16
#define OPB    16384          // bytes per operand tile (128 rows x 128B)
#define STG64  (2*OPB)        // 32768 bytes per stage (A+B)
#define GSMEM  (3*STG64)      // 98304

__device__ __forceinline__ unsigned swz128(int row, int chunk) {
    return (unsigned)(row << 7) + (unsigned)(((chunk ^ (row & 7)) & 7) << 4);
}

template<int MODE>
__device__ __forceinline__
void hgemm16_body(const __half* __restrict__ A, const __half* __restrict__ W,
                  float* __restrict__ Cf, __half* __restrict__ Ch,
                  int rowBase, int colBase, int doRope)
{
    extern __shared__ __half dsm[];
    const unsigned aSm = smem_u32(dsm);          // A at +0, B at +OPB per stage

    const int tid  = threadIdx.x;
    const int lane = tid & 31;
    const int warp = tid >> 5;
    const int grp  = lane >> 2;
    const int qk   = lane & 3;
    const int warpM = (warp & 1) * 64;
    const int warpN = (warp >> 1) * 32;
    const int lmRow = lane & 15;
    const int lmSel = lane >> 4;

    float acc[4][4][4];
#pragma unroll
    for (int mt = 0; mt < 4; ++mt)
#pragma unroll
        for (int nt = 0; nt < 4; ++nt)
#pragma unroll
            for (int r = 0; r < 4; ++r) acc[mt][nt][r] = 0.f;

    // loader: 1024 chunks (16B) per operand; 4 per thread per operand.
    // chunk id = tid + 256*i  ->  row = id>>3, chunk = id&7
    const __half* Ab = A + (size_t)rowBase * DD;
    const __half* Wb = W + (size_t)colBase * DD;

#define G_ISSUE(t, s)                                                         \
    do {                                                                      \
        const unsigned sb = aSm + (s) * STG64;                                \
        _Pragma("unroll")                                                     \
        for (int i = 0; i < 4; ++i) {                                         \
            const int id = tid + 256*i;                                       \
            const int r = id >> 3, c = id & 7;                                \
            const unsigned off = swz128(r, c);                                \
            const size_t g = (size_t)r * DD + (t)*BK64 + c*8;                 \
            CP_ASYNC16(sb + off,       Ab + g);                               \
            CP_ASYNC16(sb + OPB + off, Wb + g);                               \
        }                                                                     \
        CP_COMMIT();                                                          \
    } while (0)

    G_ISSUE(0, 0);
    G_ISSUE(1, 1);

    int buf = 0;
    for (int t = 0; t < NKT64; ++t) {
        if (t + 1 < NKT64) { CP_WAIT1(); } else { CP_WAIT0(); }
        __syncthreads();
        if (t + 2 < NKT64) G_ISSUE(t + 2, (t + 2) % 3);

        const unsigned ab = aSm + buf * STG64;
        const unsigned bb = ab + OPB;
#pragma unroll
        for (int kc = 0; kc < 4; ++kc) {
            const int ch = kc * 2 + lmSel;
            unsigned a[4][4];
#pragma unroll
            for (int mt = 0; mt < 4; ++mt)
                LDSM_X4(a[mt][0], a[mt][1], a[mt][2], a[mt][3],
                        ab + swz128(warpM + mt*16 + lmRow, ch));
            unsigned bl[4], bh[4];
#pragma unroll
            for (int nc = 0; nc < 2; ++nc) {
                unsigned x0, x1, x2, x3;
                LDSM_X4(x0, x1, x2, x3, bb + swz128(warpN + nc*16 + lmRow, ch));
                bl[2*nc] = x0; bl[2*nc+1] = x1;
                bh[2*nc] = x2; bh[2*nc+1] = x3;
            }
#pragma unroll
            for (int mt = 0; mt < 4; ++mt)
#pragma unroll
                for (int nt = 0; nt < 4; ++nt)
                    MMA_F16(acc[mt][nt][0], acc[mt][nt][1],
                            acc[mt][nt][2], acc[mt][nt][3],
                            a[mt][0], a[mt][1], a[mt][2], a[mt][3],
                            bl[nt], bh[nt]);
        }
        buf = (buf + 1) % 3;
    }
#undef G_ISSUE

    // ---- epilogue ----
#pragma unroll
    for (int mt = 0; mt < 4; ++mt) {
#pragma unroll
        for (int nt = 0; nt < 4; ++nt) {
            const int rr = rowBase + warpM + mt*16 + grp;
            const int c  = colBase + warpN + nt*8 + 2*qk;
            float2 v0 = make_float2(acc[mt][nt][0], acc[mt][nt][1]);
            float2 v1 = make_float2(acc[mt][nt][2], acc[mt][nt][3]);
            if (MODE == 0) {
                *(float2*)&Cf[(size_t)rr * DD + c]       = v0;
                *(float2*)&Cf[(size_t)(rr+8) * DD + c]   = v1;
            } else {
                const int hh = c / DH, d = c % DH;
                const int b0 = rr / TT, t0 = rr % TT;
                const int b1 = (rr+8) / TT, t1 = (rr+8) % TT;
                if (doRope) {
                    const int pair = d >> 1;
                    const float freq = powf(10000.0f, -(float)pair * (1.0f/32.0f));
                    float s0, cc0, s1, cc1;
                    sincosf((float)t0 * freq, &s0, &cc0);
                    sincosf((float)t1 * freq, &s1, &cc1);
                    v0 = make_float2(cc0*v0.x - s0*v0.y, s0*v0.x + cc0*v0.y);
                    v1 = make_float2(cc1*v1.x - s1*v1.y, s1*v1.x + cc1*v1.y);
                }
                *(unsigned*)&Ch[(((size_t)(b0*NH + hh))*TT + t0)*DH + d] =
                    pack_h2(v0.x, v0.y);
                *(unsigned*)&Ch[(((size_t)(b1*NH + hh))*TT + t1)*DH + d] =
                    pack_h2(v1.x, v1.y);
            }
        }
    }
}

__global__ __launch_bounds__(256, 2)
void hgemm16_qkv()
{
    const int z = blockIdx.z;
    __half* C = (z == 0) ? g_Qh : (z == 1) ? g_Kh : g_Vh;
    hgemm16_body<1>(g_h16, g_w16[z], nullptr, C,
                    blockIdx.y * 128, blockIdx.x * 128, z < 2);
}

__global__ __launch_bounds__(256, 2)
void hgemm16_out(float* __restrict__ out)
{
    hgemm16_body<0>(g_A16, g_w16[3], out, nullptr,
                    blockIdx.y * 128, blockIdx.x * 128, 0);
}

// ---------------------------------------------------------------------------
// fp16 tensor-core causal flash attention (R7 winner, unchanged).
// ---------------------------------------------------------------------------
#define FKST  72
#define FTILE (64*FKST*2)

__global__ __launch_bounds__(256, 2)
void flash16()
{
    __shared__ __half sK[2*64*FKST];
    __shared__ __half sV[2*64*FKST];
    const unsigned kSm = smem_u32(sK);
    const unsigned vSm = smem_u32(sV);

    const int tid  = threadIdx.x;
    const int lane = tid & 31;
    const int warp = tid >> 5;
    const int grp  = lane >> 2;
    const int qk   = lane & 3;
    const int qtile = gridDim.x - 1 - blockIdx.x;
    const int bh    = blockIdx.y;
    const int qbase = qtile * 128;

    const __half* Qp = g_Qh + (size_t)bh * TT * DH;
    const __half* Kp = g_Kh + (size_t)bh * TT * DH;
    const __half* Vp = g_Vh + (size_t)bh * TT * DH;

    const int lmRow = lane & 15;
    const int lmSel = lane >> 4;

    const int qi0 = qbase + warp*16 + grp;
    const int qi1 = qi0 + 8;
    unsigned qa[4][4];
    {
        const __half* q0 = Qp + (size_t)qi0 * DH;
        const __half* q1 = Qp + (size_t)qi1 * DH;
#pragma unroll
        for (int kc = 0; kc < 4; ++kc) {
            qa[kc][0] = *(const unsigned*)(q0 + kc*16 + 2*qk);
            qa[kc][1] = *(const unsigned*)(q1 + kc*16 + 2*qk);
            qa[kc][2] = *(const unsigned*)(q0 + kc*16 + 8 + 2*qk);
            qa[kc][3] = *(const unsigned*)(q1 + kc*16 + 8 + 2*qk);
        }
    }

    float m0 = -1e30f, m1 = -1e30f, l0 = 0.f, l1 = 0.f;
    float oa[8][4];
#pragma unroll
    for (int nt = 0; nt < 8; ++nt)
#pragma unroll
        for (int r = 0; r < 4; ++r) oa[nt][r] = 0.f;

    const int fr = tid >> 3;
    const int fc = tid & 7;
    const unsigned dk0 = (fr*FKST + fc*8) * 2;
    const unsigned dk1 = ((fr+32)*FKST + fc*8) * 2;

#define F_ISSUE(kt, s)                                                        \
    do {                                                                      \
        const __half* ks_ = Kp + (size_t)((kt)*64 + fr) * DH + fc*8;          \
        const __half* vs_ = Vp + (size_t)((kt)*64 + fr) * DH + fc*8;          \
        CP_ASYNC16(kSm + (s)*FTILE + dk0, ks_);                               \
        CP_ASYNC16(kSm + (s)*FTILE + dk1, ks_ + (size_t)32*DH);               \
        CP_ASYNC16(vSm + (s)*FTILE + dk0, vs_);                               \
        CP_ASYNC16(vSm + (s)*FTILE + dk1, vs_ + (size_t)32*DH);               \
        CP_COMMIT();                                                          \
    } while (0)

    F_ISSUE(0, 0);

    const int lastKt = 2*qtile + 1;
    for (int kt = 0; kt <= lastKt; ++kt) {
        const int kbase = kt * 64;
        const int s = kt & 1;
        CP_WAIT0();
        __syncthreads();
        if (kt < lastKt) F_ISSUE(kt + 1, (kt + 1) & 1);

        float sa[8][4];
#pragma unroll
        for (int nt = 0; nt < 8; ++nt)
#pragma unroll
            for (int r = 0; r < 4; ++r) sa[nt][r] = 0.f;

#pragma unroll
        for (int kc = 0; kc < 4; ++kc) {
#pragma unroll
            for (int nc = 0; nc < 4; ++nc) {
                unsigned x0, x1, x2, x3;
                const unsigned addr = kSm + s*FTILE +
                    ((nc*16 + lmRow)*FKST + (kc*2 + lmSel)*8) * 2;
                LDSM_X4(x0, x1, x2, x3, addr);
                MMA_F16(sa[2*nc  ][0], sa[2*nc  ][1], sa[2*nc  ][2], sa[2*nc  ][3],
                        qa[kc][0], qa[kc][1], qa[kc][2], qa[kc][3], x0, x2);
                MMA_F16(sa[2*nc+1][0], sa[2*nc+1][1], sa[2*nc+1][2], sa[2*nc+1][3],
                        qa[kc][0], qa[kc][1], qa[kc][2], qa[kc][3], x1, x3);
            }
        }

        const float sc = 0.125f;
        if (kbase + 63 > qbase) {
#pragma unroll
            for (int nt = 0; nt < 8; ++nt) {
                const int c0 = kbase + nt*8 + 2*qk;
                const int c1 = c0 + 1;
                sa[nt][0] = (c0 <= qi0) ? sa[nt][0]*sc : -1e30f;
                sa[nt][1] = (c1 <= qi0) ? sa[nt][1]*sc : -1e30f;
                sa[nt][2] = (c0 <= qi1) ? sa[nt][2]*sc : -1e30f;
                sa[nt][3] = (c1 <= qi1) ? sa[nt][3]*sc : -1e30f;
            }
        } else {
#pragma unroll
            for (int nt = 0; nt < 8; ++nt)
#pragma unroll
                for (int r = 0; r < 4; ++r) sa[nt][r] *= sc;
        }

        float mx0 = sa[0][0], mx1 = sa[0][2];
#pragma unroll
        for (int nt = 0; nt < 8; ++nt) {
            mx0 = fmaxf(mx0, fmaxf(sa[nt][0], sa[nt][1]));
            mx1 = fmaxf(mx1, fmaxf(sa[nt][2], sa[nt][3]));
        }
        mx0 = fmaxf(mx0, __shfl_xor_sync(0xffffffffu, mx0, 1));
        mx0 = fmaxf(mx0, __shfl_xor_sync(0xffffffffu, mx0, 2));
        mx1 = fmaxf(mx1, __shfl_xor_sync(0xffffffffu, mx1, 1));
        mx1 = fmaxf(mx1, __shfl_xor_sync(0xffffffffu, mx1, 2));

        const float nm0 = fmaxf(m0, mx0);
        const float nm1 = fmaxf(m1, mx1);
        const float al0 = __expf(m0 - nm0);
        const float al1 = __expf(m1 - nm1);
        m0 = nm0; m1 = nm1;

        float rs0 = 0.f, rs1 = 0.f;
#pragma unroll
        for (int nt = 0; nt < 8; ++nt) {
            sa[nt][0] = __expf(sa[nt][0] - nm0);
            sa[nt][1] = __expf(sa[nt][1] - nm0);
            sa[nt][2] = __expf(sa[nt][2] - nm1);
            sa[nt][3] = __expf(sa[nt][3] - nm1);
            rs0 += sa[nt][0] + sa[nt][1];
            rs1 += sa[nt][2] + sa[nt][3];
        }
        rs0 += __shfl_xor_sync(0xffffffffu, rs0, 1);
        rs0 += __shfl_xor_sync(0xffffffffu, rs0, 2);
        rs1 += __shfl_xor_sync(0xffffffffu, rs1, 1);
        rs1 += __shfl_xor_sync(0xffffffffu, rs1, 2);
        l0 = l0*al0 + rs0;
        l1 = l1*al1 + rs1;

#pragma unroll
        for (int nt = 0; nt < 8; ++nt) {
            oa[nt][0] *= al0; oa[nt][1] *= al0;
            oa[nt][2] *= al1; oa[nt][3] *= al1;
        }

#pragma unroll
        for (int kc = 0; kc < 4; ++kc) {
            const unsigned a0 = pack_h2(sa[2*kc  ][0], sa[2*kc  ][1]);
            const unsigned a1 = pack_h2(sa[2*kc  ][2], sa[2*kc  ][3]);
            const unsigned a2 = pack_h2(sa[2*kc+1][0], sa[2*kc+1][1]);
            const unsigned a3 = pack_h2(sa[2*kc+1][2], sa[2*kc+1][3]);
            const unsigned raddr = vSm + s*FTILE +
                (((kc*16 + lmRow) * FKST) + lmSel*8) * 2;
#pragma unroll
            for (int np = 0; np < 4; ++np) {
                unsigned b0, b1, b2, b3;
                LDSM_X4_TRANS(b0, b1, b2, b3, raddr + np*32);
                MMA_F16(oa[2*np  ][0], oa[2*np  ][1], oa[2*np  ][2], oa[2*np  ][3],
                        a0, a1, a2, a3, b0, b1);
                MMA_F16(oa[2*np+1][0], oa[2*np+1][1], oa[2*np+1][2], oa[2*np+1][3],
                        a0, a1, a2, a3, b2, b3);
            }
        }
    }
#undef F_ISSUE

    const int b = bh / NH, hh = bh % NH;
    const float inv0 = 1.f / l0;
    const float inv1 = 1.f / l1;
    __half* d0 = g_A16 + ((size_t)(b*TT + qi0))*DD + hh*DH;
    __half* d1 = g_A16 + ((size_t)(b*TT + qi1))*DD + hh*DH;
#pragma unroll
    for (int nt = 0; nt < 8; ++nt) {
        const int c = nt*8 + 2*qk;
        *(unsigned*)&d0[c] = pack_h2(oa[nt][0]*inv0, oa[nt][1]*inv0);
        *(unsigned*)&d1[c] = pack_h2(oa[nt][2]*inv1, oa[nt][3]*inv1);
    }
}

// ---------------------------------------------------------------------------
extern "C" void kernel_launch(void* const* d_in, const int* in_sizes, int n_in,
                              void* d_out, int out_size)
{
    const float* h  = (const float*)d_in[0];
    const float* wq = (const float*)d_in[1];
    const float* wk = (const float*)d_in[2];
    const float* wv = (const float*)d_in[3];
    const float* wo = (const float*)d_in[4];
    float* out = (float*)d_out;
    (void)in_sizes; (void)n_in; (void)out_size;

    cudaFuncSetAttribute(hgemm16_qkv, cudaFuncAttributeMaxDynamicSharedMemorySize, GSMEM);
    cudaFuncSetAttribute(hgemm16_out, cudaFuncAttributeMaxDynamicSharedMemorySize, GSMEM);

    cvt5<<<dim3(BT*DD/(256*8), 5), 256>>>(h, wq, wk, wv, wo);

    hgemm16_qkv<<<dim3(DD/128, BT/128, 3), 256, GSMEM>>>();

    flash16<<<dim3(TT/128, BB*NH), 256>>>();

    hgemm16_out<<<dim3(DD/128, BT/128), 256, GSMEM>>>(out);
}

// round 11
// speedup vs baseline: 8.6902x; 1.0496x over previous
#include <cuda_runtime.h>
#include <cuda_fp16.h>
#include <math.h>

#define BB 2
#define TT 2048
#define DD 1024
#define NH 16
#define DH 64
#define BT (BB*TT)

// fp16 scratch (allocation-free rule: __device__ globals)
__device__ __align__(16) __half g_h16[BT*DD];
__device__ __align__(16) __half g_w16[4][DD*DD];
__device__ __align__(16) __half g_Qh[BB*NH*TT*DH];
__device__ __align__(16) __half g_Kh[BB*NH*TT*DH];
__device__ __align__(16) __half g_Vh[BB*NH*TT*DH];
__device__ __align__(16) __half g_A16[BT*DD];

__device__ __forceinline__ unsigned pack_h2(float x, float y) {
    unsigned r;
    asm("cvt.rn.f16x2.f32 %0, %1, %2;" : "=r"(r) : "f"(y), "f"(x));
    return r;
}
__device__ __forceinline__ unsigned smem_u32(const void* p) {
    return (unsigned)__cvta_generic_to_shared(p);
}
__device__ __forceinline__ float fex2(float x) {
    float r;
    asm("ex2.approx.f32 %0, %1;" : "=f"(r) : "f"(x));
    return r;
}
#define H2EX2(d, s) asm("ex2.approx.f16x2 %0, %1;" : "=r"(d) : "r"(s))

#define MMA_F16(d0,d1,d2,d3,a0,a1,a2,a3,b0,b1)                                    \
    asm volatile("mma.sync.aligned.m16n8k16.row.col.f32.f16.f16.f32 "             \
                 "{%0,%1,%2,%3},{%4,%5,%6,%7},{%8,%9},{%0,%1,%2,%3};"             \
                 : "+f"(d0), "+f"(d1), "+f"(d2), "+f"(d3)                         \
                 : "r"(a0), "r"(a1), "r"(a2), "r"(a3), "r"(b0), "r"(b1))

#define LDSM_X4(r0,r1,r2,r3,addr)                                                 \
    asm volatile("ldmatrix.sync.aligned.m8n8.x4.shared.b16 "                      \
                 "{%0,%1,%2,%3}, [%4];"                                           \
                 : "=r"(r0), "=r"(r1), "=r"(r2), "=r"(r3) : "r"(addr))

#define LDSM_X4_TRANS(r0,r1,r2,r3,addr)                                           \
    asm volatile("ldmatrix.sync.aligned.m8n8.x4.trans.shared.b16 "                \
                 "{%0,%1,%2,%3}, [%4];"                                           \
                 : "=r"(r0), "=r"(r1), "=r"(r2), "=r"(r3) : "r"(addr))

#define LDSM_X2_TRANS(r0,r1,addr)                                                 \
    asm volatile("ldmatrix.sync.aligned.m8n8.x2.trans.shared.b16 "                \
                 "{%0,%1}, [%2];"                                                 \
                 : "=r"(r0), "=r"(r1) : "r"(addr))

#define CP_ASYNC16(dst, src)                                                      \
    asm volatile("cp.async.cg.shared.global [%0], [%1], 16;" :: "r"(dst), "l"(src))
#define CP_COMMIT() asm volatile("cp.async.commit_group;")
#define CP_WAIT0()  asm volatile("cp.async.wait_group 0;")
#define CP_WAIT1()  asm volatile("cp.async.wait_group 1;")

// ---------------------------------------------------------------------------
// fp32 -> fp16 conversion: segment 0 = h (4M), 1-4 = weights (1M each)
// ---------------------------------------------------------------------------
__global__ void cvt5(const float* __restrict__ h,  const float* __restrict__ wq,
                     const float* __restrict__ wk, const float* __restrict__ wv,
                     const float* __restrict__ wo)
{
    const float* src; __half* dst; int n;
    switch (blockIdx.y) {
        case 0: src = h;  dst = g_h16;     n = BT*DD; break;
        case 1: src = wq; dst = g_w16[0];  n = DD*DD; break;
        case 2: src = wk; dst = g_w16[1];  n = DD*DD; break;
        case 3: src = wv; dst = g_w16[2];  n = DD*DD; break;
        default:src = wo; dst = g_w16[3];  n = DD*DD; break;
    }
    const int idx = (blockIdx.x * blockDim.x + threadIdx.x) * 8;
    if (idx >= n) return;
    float4 v0 = *(const float4*)(src + idx);
    float4 v1 = *(const float4*)(src + idx + 4);
    uint4 u = make_uint4(pack_h2(v0.x, v0.y), pack_h2(v0.z, v0.w),
                         pack_h2(v1.x, v1.y), pack_h2(v1.z, v1.w));
    *(uint4*)&dst[idx] = u;
}

// ---------------------------------------------------------------------------
// fp16 cp.async GEMM NT (R9 winner, unchanged): BK=64, 3-stage pipeline.
// ---------------------------------------------------------------------------
#define BK64   64
#define NKT64  (DD/BK64)      // 16
#define OPB    16384          // bytes per operand tile (128 rows x 128B)
#define STG64  (2*OPB)        // 32768 bytes per stage (A+B)
#define GSMEM  (3*STG64)      // 98304

__device__ __forceinline__ unsigned swz128(int row, int chunk) {
    return (unsigned)(row << 7) + (unsigned)(((chunk ^ (row & 7)) & 7) << 4);
}

template<int MODE>
__device__ __forceinline__
void hgemm16_body(const __half* __restrict__ A, const __half* __restrict__ W,
                  float* __restrict__ Cf, __half* __restrict__ Ch,
                  int rowBase, int colBase, int doRope)
{
    extern __shared__ __half dsm[];
    const unsigned aSm = smem_u32(dsm);

    const int tid  = threadIdx.x;
    const int lane = tid & 31;
    const int warp = tid >> 5;
    const int grp  = lane >> 2;
    const int qk   = lane & 3;
    const int warpM = (warp & 1) * 64;
    const int warpN = (warp >> 1) * 32;
    const int lmRow = lane & 15;
    const int lmSel = lane >> 4;

    float acc[4][4][4];
#pragma unroll
    for (int mt = 0; mt < 4; ++mt)
#pragma unroll
        for (int nt = 0; nt < 4; ++nt)
#pragma unroll
            for (int r = 0; r < 4; ++r) acc[mt][nt][r] = 0.f;

    const __half* Ab = A + (size_t)rowBase * DD;
    const __half* Wb = W + (size_t)colBase * DD;

#define G_ISSUE(t, s)                                                         \
    do {                                                                      \
        const unsigned sb = aSm + (s) * STG64;                                \
        _Pragma("unroll")                                                     \
        for (int i = 0; i < 4; ++i) {                                         \
            const int id = tid + 256*i;                                       \
            const int r = id >> 3, c = id & 7;                                \
            const unsigned off = swz128(r, c);                                \
            const size_t g = (size_t)r * DD + (t)*BK64 + c*8;                 \
            CP_ASYNC16(sb + off,       Ab + g);                               \
            CP_ASYNC16(sb + OPB + off, Wb + g);                               \
        }                                                                     \
        CP_COMMIT();                                                          \
    } while (0)

    G_ISSUE(0, 0);
    G_ISSUE(1, 1);

    int buf = 0;
    for (int t = 0; t < NKT64; ++t) {
        if (t + 1 < NKT64) { CP_WAIT1(); } else { CP_WAIT0(); }
        __syncthreads();
        if (t + 2 < NKT64) G_ISSUE(t + 2, (t + 2) % 3);

        const unsigned ab = aSm + buf * STG64;
        const unsigned bb = ab + OPB;
#pragma unroll
        for (int kc = 0; kc < 4; ++kc) {
            const int ch = kc * 2 + lmSel;
            unsigned a[4][4];
#pragma unroll
            for (int mt = 0; mt < 4; ++mt)
                LDSM_X4(a[mt][0], a[mt][1], a[mt][2], a[mt][3],
                        ab + swz128(warpM + mt*16 + lmRow, ch));
            unsigned bl[4], bh[4];
#pragma unroll
            for (int nc = 0; nc < 2; ++nc) {
                unsigned x0, x1, x2, x3;
                LDSM_X4(x0, x1, x2, x3, bb + swz128(warpN + nc*16 + lmRow, ch));
                bl[2*nc] = x0; bl[2*nc+1] = x1;
                bh[2*nc] = x2; bh[2*nc+1] = x3;
            }
#pragma unroll
            for (int mt = 0; mt < 4; ++mt)
#pragma unroll
                for (int nt = 0; nt < 4; ++nt)
                    MMA_F16(acc[mt][nt][0], acc[mt][nt][1],
                            acc[mt][nt][2], acc[mt][nt][3],
                            a[mt][0], a[mt][1], a[mt][2], a[mt][3],
                            bl[nt], bh[nt]);
        }
        buf = (buf + 1) % 3;
    }
#undef G_ISSUE

#pragma unroll
    for (int mt = 0; mt < 4; ++mt) {
#pragma unroll
        for (int nt = 0; nt < 4; ++nt) {
            const int rr = rowBase + warpM + mt*16 + grp;
            const int c  = colBase + warpN + nt*8 + 2*qk;
            float2 v0 = make_float2(acc[mt][nt][0], acc[mt][nt][1]);
            float2 v1 = make_float2(acc[mt][nt][2], acc[mt][nt][3]);
            if (MODE == 0) {
                *(float2*)&Cf[(size_t)rr * DD + c]       = v0;
                *(float2*)&Cf[(size_t)(rr+8) * DD + c]   = v1;
            } else {
                const int hh = c / DH, d = c % DH;
                const int b0 = rr / TT, t0 = rr % TT;
                const int b1 = (rr+8) / TT, t1 = (rr+8) % TT;
                if (doRope) {
                    const int pair = d >> 1;
                    const float freq = powf(10000.0f, -(float)pair * (1.0f/32.0f));
                    float s0, cc0, s1, cc1;
                    sincosf((float)t0 * freq, &s0, &cc0);
                    sincosf((float)t1 * freq, &s1, &cc1);
                    v0 = make_float2(cc0*v0.x - s0*v0.y, s0*v0.x + cc0*v0.y);
                    v1 = make_float2(cc1*v1.x - s1*v1.y, s1*v1.x + cc1*v1.y);
                }
                *(unsigned*)&Ch[(((size_t)(b0*NH + hh))*TT + t0)*DH + d] =
                    pack_h2(v0.x, v0.y);
                *(unsigned*)&Ch[(((size_t)(b1*NH + hh))*TT + t1)*DH + d] =
                    pack_h2(v1.x, v1.y);
            }
        }
    }
}

__global__ __launch_bounds__(256, 2)
void hgemm16_qkv()
{
    const int z = blockIdx.z;
    __half* C = (z == 0) ? g_Qh : (z == 1) ? g_Kh : g_Vh;
    hgemm16_body<1>(g_h16, g_w16[z], nullptr, C,
                    blockIdx.y * 128, blockIdx.x * 128, z < 2);
}

__global__ __launch_bounds__(256, 2)
void hgemm16_out(float* __restrict__ out)
{
    hgemm16_body<0>(g_A16, g_w16[3], out, nullptr,
                    blockIdx.y * 128, blockIdx.x * 128, 0);
}

// ---------------------------------------------------------------------------
// fp16 flash attention, log2-domain softmax:
//  - scores scaled by (1/sqrt(dh))*log2(e); P = ex2.approx.f16x2(s - m)
//    (masked: -1e30 -> f16 -inf -> ex2 -> +0)
//  - row-sum l via ones-column MMA: V smem pad col 64 = 1.0 (set once;
//    cp.async never writes cols 64-71), accumulated in fp32 with the same
//    al-rescaling as O => exact online-softmax l of the actual fp16 P.
// ---------------------------------------------------------------------------
#define FKST  72
#define FTILE (64*FKST*2)

__global__ __launch_bounds__(256, 2)
void flash16()
{
    __shared__ __half sK[2*64*FKST];
    __shared__ __half sV[2*64*FKST];
    const unsigned kSm = smem_u32(sK);
    const unsigned vSm = smem_u32(sV);

    const int tid  = threadIdx.x;
    const int lane = tid & 31;
    const int warp = tid >> 5;
    const int grp  = lane >> 2;
    const int qk   = lane & 3;
    const int qtile = gridDim.x - 1 - blockIdx.x;
    const int bh    = blockIdx.y;
    const int qbase = qtile * 128;

    const __half* Qp = g_Qh + (size_t)bh * TT * DH;
    const __half* Kp = g_Kh + (size_t)bh * TT * DH;
    const __half* Vp = g_Vh + (size_t)bh * TT * DH;

    const int lmRow = lane & 15;
    const int lmSel = lane >> 4;

    const int qi0 = qbase + warp*16 + grp;
    const int qi1 = qi0 + 8;
    unsigned qa[4][4];
    {
        const __half* q0 = Qp + (size_t)qi0 * DH;
        const __half* q1 = Qp + (size_t)qi1 * DH;
#pragma unroll
        for (int kc = 0; kc < 4; ++kc) {
            qa[kc][0] = *(const unsigned*)(q0 + kc*16 + 2*qk);
            qa[kc][1] = *(const unsigned*)(q1 + kc*16 + 2*qk);
            qa[kc][2] = *(const unsigned*)(q0 + kc*16 + 8 + 2*qk);
            qa[kc][3] = *(const unsigned*)(q1 + kc*16 + 8 + 2*qk);
        }
    }

    float m0 = -1e30f, m1 = -1e30f;
    float oa[8][4];
    float oaS[4] = {0.f, 0.f, 0.f, 0.f};     // ones-column accumulator (l)
#pragma unroll
    for (int nt = 0; nt < 8; ++nt)
#pragma unroll
        for (int r = 0; r < 4; ++r) oa[nt][r] = 0.f;

    // V pad init: col 64 = 1.0, cols 65-71 = 0, both stages (persistent:
    // cp.async below only writes cols 0-63).
    if (tid < 128) {
        const int rr = tid & 63, ss = tid >> 6;
        *(uint4*)&sV[ss*64*FKST + rr*FKST + 64] = make_uint4(0x00003C00u, 0u, 0u, 0u);
    }

    const int fr = tid >> 3;
    const int fc = tid & 7;
    const unsigned dk0 = (fr*FKST + fc*8) * 2;
    const unsigned dk1 = ((fr+32)*FKST + fc*8) * 2;

#define F_ISSUE(kt, s)                                                        \
    do {                                                                      \
        const __half* ks_ = Kp + (size_t)((kt)*64 + fr) * DH + fc*8;          \
        const __half* vs_ = Vp + (size_t)((kt)*64 + fr) * DH + fc*8;          \
        CP_ASYNC16(kSm + (s)*FTILE + dk0, ks_);                               \
        CP_ASYNC16(kSm + (s)*FTILE + dk1, ks_ + (size_t)32*DH);               \
        CP_ASYNC16(vSm + (s)*FTILE + dk0, vs_);                               \
        CP_ASYNC16(vSm + (s)*FTILE + dk1, vs_ + (size_t)32*DH);               \
        CP_COMMIT();                                                          \
    } while (0)

    F_ISSUE(0, 0);

    const int lastKt = 2*qtile + 1;
    for (int kt = 0; kt <= lastKt; ++kt) {
        const int kbase = kt * 64;
        const int s = kt & 1;
        CP_WAIT0();
        __syncthreads();
        if (kt < lastKt) F_ISSUE(kt + 1, (kt + 1) & 1);

        // ---- S = Q K^T ----
        float sa[8][4];
#pragma unroll
        for (int nt = 0; nt < 8; ++nt)
#pragma unroll
            for (int r = 0; r < 4; ++r) sa[nt][r] = 0.f;

#pragma unroll
        for (int kc = 0; kc < 4; ++kc) {
#pragma unroll
            for (int nc = 0; nc < 4; ++nc) {
                unsigned x0, x1, x2, x3;
                const unsigned addr = kSm + s*FTILE +
                    ((nc*16 + lmRow)*FKST + (kc*2 + lmSel)*8) * 2;
                LDSM_X4(x0, x1, x2, x3, addr);
                MMA_F16(sa[2*nc  ][0], sa[2*nc  ][1], sa[2*nc  ][2], sa[2*nc  ][3],
                        qa[kc][0], qa[kc][1], qa[kc][2], qa[kc][3], x0, x2);
                MMA_F16(sa[2*nc+1][0], sa[2*nc+1][1], sa[2*nc+1][2], sa[2*nc+1][3],
                        qa[kc][0], qa[kc][1], qa[kc][2], qa[kc][3], x1, x3);
            }
        }

        // ---- scale into log2 domain + causal mask ----
        const float sc2 = 0.125f * 1.44269504f;   // (1/sqrt(dh))*log2(e)
        if (kbase + 63 > qbase) {
#pragma unroll
            for (int nt = 0; nt < 8; ++nt) {
                const int c0 = kbase + nt*8 + 2*qk;
                const int c1 = c0 + 1;
                sa[nt][0] = (c0 <= qi0) ? sa[nt][0]*sc2 : -1e30f;
                sa[nt][1] = (c1 <= qi0) ? sa[nt][1]*sc2 : -1e30f;
                sa[nt][2] = (c0 <= qi1) ? sa[nt][2]*sc2 : -1e30f;
                sa[nt][3] = (c1 <= qi1) ? sa[nt][3]*sc2 : -1e30f;
            }
        } else {
#pragma unroll
            for (int nt = 0; nt < 8; ++nt)
#pragma unroll
                for (int r = 0; r < 4; ++r) sa[nt][r] *= sc2;
        }

        // ---- row max + rescale factor (log2 domain) ----
        float mx0 = sa[0][0], mx1 = sa[0][2];
#pragma unroll
        for (int nt = 0; nt < 8; ++nt) {
            mx0 = fmaxf(mx0, fmaxf(sa[nt][0], sa[nt][1]));
            mx1 = fmaxf(mx1, fmaxf(sa[nt][2], sa[nt][3]));
        }
        mx0 = fmaxf(mx0, __shfl_xor_sync(0xffffffffu, mx0, 1));
        mx0 = fmaxf(mx0, __shfl_xor_sync(0xffffffffu, mx0, 2));
        mx1 = fmaxf(mx1, __shfl_xor_sync(0xffffffffu, mx1, 1));
        mx1 = fmaxf(mx1, __shfl_xor_sync(0xffffffffu, mx1, 2));

        const float nm0 = fmaxf(m0, mx0);
        const float nm1 = fmaxf(m1, mx1);
        const float al0 = fex2(m0 - nm0);
        const float al1 = fex2(m1 - nm1);
        m0 = nm0; m1 = nm1;

#pragma unroll
        for (int nt = 0; nt < 8; ++nt) {
            oa[nt][0] *= al0; oa[nt][1] *= al0;
            oa[nt][2] *= al1; oa[nt][3] *= al1;
        }
        oaS[0] *= al0; oaS[1] *= al0;
        oaS[2] *= al1; oaS[3] *= al1;

        // ---- O += P V, l += P·1 : P = ex2.f16x2(s - m), in-register ----
#pragma unroll
        for (int kc = 0; kc < 4; ++kc) {
            unsigned a0 = pack_h2(sa[2*kc  ][0] - nm0, sa[2*kc  ][1] - nm0);
            unsigned a1 = pack_h2(sa[2*kc  ][2] - nm1, sa[2*kc  ][3] - nm1);
            unsigned a2 = pack_h2(sa[2*kc+1][0] - nm0, sa[2*kc+1][1] - nm0);
            unsigned a3 = pack_h2(sa[2*kc+1][2] - nm1, sa[2*kc+1][3] - nm1);
            H2EX2(a0, a0); H2EX2(a1, a1); H2EX2(a2, a2); H2EX2(a3, a3);

            const unsigned raddr = vSm + s*FTILE +
                (((kc*16 + lmRow) * FKST) + lmSel*8) * 2;
#pragma unroll
            for (int np = 0; np < 4; ++np) {
                unsigned b0, b1, b2, b3;
                LDSM_X4_TRANS(b0, b1, b2, b3, raddr + np*32);
                MMA_F16(oa[2*np  ][0], oa[2*np  ][1], oa[2*np  ][2], oa[2*np  ][3],
                        a0, a1, a2, a3, b0, b1);
                MMA_F16(oa[2*np+1][0], oa[2*np+1][1], oa[2*np+1][2], oa[2*np+1][3],
                        a0, a1, a2, a3, b2, b3);
            }
            // ones-column (cols 64-71 of V smem rows): row-sum into oaS
            unsigned s0, s1;
            LDSM_X2_TRANS(s0, s1, vSm + s*FTILE + ((kc*16 + lmRow)*FKST + 64)*2);
            MMA_F16(oaS[0], oaS[1], oaS[2], oaS[3], a0, a1, a2, a3, s0, s1);
        }
    }
#undef F_ISSUE

    // ---- epilogue: l lives in quad-lane-0's oaS (col 64) ----
    const float l0 = __shfl_sync(0xffffffffu, oaS[0], lane & ~3);
    const float l1 = __shfl_sync(0xffffffffu, oaS[2], lane & ~3);
    const int b = bh / NH, hh = bh % NH;
    const float inv0 = 1.f / l0;
    const float inv1 = 1.f / l1;
    __half* d0 = g_A16 + ((size_t)(b*TT + qi0))*DD + hh*DH;
    __half* d1 = g_A16 + ((size_t)(b*TT + qi1))*DD + hh*DH;
#pragma unroll
    for (int nt = 0; nt < 8; ++nt) {
        const int c = nt*8 + 2*qk;
        *(unsigned*)&d0[c] = pack_h2(oa[nt][0]*inv0, oa[nt][1]*inv0);
        *(unsigned*)&d1[c] = pack_h2(oa[nt][2]*inv1, oa[nt][3]*inv1);
    }
}

// ---------------------------------------------------------------------------
extern "C" void kernel_launch(void* const* d_in, const int* in_sizes, int n_in,
                              void* d_out, int out_size)
{
    const float* h  = (const float*)d_in[0];
    const float* wq = (const float*)d_in[1];
    const float* wk = (const float*)d_in[2];
    const float* wv = (const float*)d_in[3];
    const float* wo = (const float*)d_in[4];
    float* out = (float*)d_out;
    (void)in_sizes; (void)n_in; (void)out_size;

    cudaFuncSetAttribute(hgemm16_qkv, cudaFuncAttributeMaxDynamicSharedMemorySize, GSMEM);
    cudaFuncSetAttribute(hgemm16_out, cudaFuncAttributeMaxDynamicSharedMemorySize, GSMEM);

    cvt5<<<dim3(BT*DD/(256*8), 5), 256>>>(h, wq, wk, wv, wo);

    hgemm16_qkv<<<dim3(DD/128, BT/128, 3), 256, GSMEM>>>();

    flash16<<<dim3(TT/128, BB*NH), 256>>>();

    hgemm16_out<<<dim3(DD/128, BT/128), 256, GSMEM>>>(out);
}

// round 12
// speedup vs baseline: 8.7293x; 1.0045x over previous
#include <cuda_runtime.h>
#include <cuda_fp16.h>
#include <math.h>

#define BB 2
#define TT 2048
#define DD 1024
#define NH 16
#define DH 64
#define BT (BB*TT)

// fp16 scratch (allocation-free rule: __device__ globals)
__device__ __align__(16) __half g_h16[BT*DD];
__device__ __align__(16) __half g_w16[4][DD*DD];
__device__ __align__(16) __half g_Qh[BB*NH*TT*DH];
__device__ __align__(16) __half g_Kh[BB*NH*TT*DH];
__device__ __align__(16) __half g_Vh[BB*NH*TT*DH];
__device__ __align__(16) __half g_A16[BT*DD];

__device__ __forceinline__ unsigned pack_h2(float x, float y) {
    unsigned r;
    asm("cvt.rn.f16x2.f32 %0, %1, %2;" : "=r"(r) : "f"(y), "f"(x));
    return r;
}
__device__ __forceinline__ unsigned smem_u32(const void* p) {
    return (unsigned)__cvta_generic_to_shared(p);
}
__device__ __forceinline__ float fex2(float x) {
    float r;
    asm("ex2.approx.f32 %0, %1;" : "=f"(r) : "f"(x));
    return r;
}
#define H2EX2(d, s) asm("ex2.approx.f16x2 %0, %1;" : "=r"(d) : "r"(s))

#define MMA_F16(d0,d1,d2,d3,a0,a1,a2,a3,b0,b1)                                    \
    asm volatile("mma.sync.aligned.m16n8k16.row.col.f32.f16.f16.f32 "             \
                 "{%0,%1,%2,%3},{%4,%5,%6,%7},{%8,%9},{%0,%1,%2,%3};"             \
                 : "+f"(d0), "+f"(d1), "+f"(d2), "+f"(d3)                         \
                 : "r"(a0), "r"(a1), "r"(a2), "r"(a3), "r"(b0), "r"(b1))

#define LDSM_X4(r0,r1,r2,r3,addr)                                                 \
    asm volatile("ldmatrix.sync.aligned.m8n8.x4.shared.b16 "                      \
                 "{%0,%1,%2,%3}, [%4];"                                           \
                 : "=r"(r0), "=r"(r1), "=r"(r2), "=r"(r3) : "r"(addr))

#define LDSM_X4_TRANS(r0,r1,r2,r3,addr)                                           \
    asm volatile("ldmatrix.sync.aligned.m8n8.x4.trans.shared.b16 "                \
                 "{%0,%1,%2,%3}, [%4];"                                           \
                 : "=r"(r0), "=r"(r1), "=r"(r2), "=r"(r3) : "r"(addr))

#define LDSM_X2_TRANS(r0,r1,addr)                                                 \
    asm volatile("ldmatrix.sync.aligned.m8n8.x2.trans.shared.b16 "                \
                 "{%0,%1}, [%2];"                                                 \
                 : "=r"(r0), "=r"(r1) : "r"(addr))

#define CP_ASYNC16(dst, src)                                                      \
    asm volatile("cp.async.cg.shared.global [%0], [%1], 16;" :: "r"(dst), "l"(src))
#define CP_COMMIT() asm volatile("cp.async.commit_group;")
#define CP_WAIT0()  asm volatile("cp.async.wait_group 0;")
#define CP_WAIT1()  asm volatile("cp.async.wait_group 1;")

// ---------------------------------------------------------------------------
// fp32 -> fp16 conversion: segment 0 = h (4M), 1-4 = weights (1M each)
// ---------------------------------------------------------------------------
__global__ void cvt5(const float* __restrict__ h,  const float* __restrict__ wq,
                     const float* __restrict__ wk, const float* __restrict__ wv,
                     const float* __restrict__ wo)
{
    const float* src; __half* dst; int n;
    switch (blockIdx.y) {
        case 0: src = h;  dst = g_h16;     n = BT*DD; break;
        case 1: src = wq; dst = g_w16[0];  n = DD*DD; break;
        case 2: src = wk; dst = g_w16[1];  n = DD*DD; break;
        case 3: src = wv; dst = g_w16[2];  n = DD*DD; break;
        default:src = wo; dst = g_w16[3];  n = DD*DD; break;
    }
    const int idx = (blockIdx.x * blockDim.x + threadIdx.x) * 8;
    if (idx >= n) return;
    float4 v0 = *(const float4*)(src + idx);
    float4 v1 = *(const float4*)(src + idx + 4);
    uint4 u = make_uint4(pack_h2(v0.x, v0.y), pack_h2(v0.z, v0.w),
                         pack_h2(v1.x, v1.y), pack_h2(v1.z, v1.w));
    *(uint4*)&dst[idx] = u;
}

// ---------------------------------------------------------------------------
// fp16 cp.async GEMM NT: C = A[M,K] * W[N,K]^T, fp32 accum.
// CTA tile 128x64, BK=64, 3-stage pipeline, 256 thr = 8 warps (4 M x 2 N),
// warp tile 32x32 (acc = 32 regs) -> 3 CTAs/SM (24 warps).
// Canonical SW128 swizzle, ldmatrix.x4, m16n8k16.
// MODE 0: fp32 C row-major.  MODE 1: fp16 C head layout + optional RoPE.
// ---------------------------------------------------------------------------
#define BKG    64
#define NKTG   (DD/BKG)       // 16
#define OPA    16384          // A tile: 128 rows x 128B
#define OPBB   8192           // B tile:  64 rows x 128B
#define STGG   (OPA + OPBB)   // 24576 per stage
#define GSMEM  (3*STGG)       // 73728

__device__ __forceinline__ unsigned swz128(int row, int chunk) {
    return (unsigned)(row << 7) + (unsigned)(((chunk ^ (row & 7)) & 7) << 4);
}

template<int MODE>
__device__ __forceinline__
void hgemm16_body(const __half* __restrict__ A, const __half* __restrict__ W,
                  float* __restrict__ Cf, __half* __restrict__ Ch,
                  int rowBase, int colBase, int doRope)
{
    extern __shared__ __half dsm[];
    const unsigned aSm = smem_u32(dsm);

    const int tid  = threadIdx.x;
    const int lane = tid & 31;
    const int warp = tid >> 5;
    const int grp  = lane >> 2;
    const int qk   = lane & 3;
    const int warpM = (warp & 3) * 32;      // 4 M-slots
    const int warpN = (warp >> 2) * 32;     // 2 N-slots
    const int lmRow = lane & 15;
    const int lmSel = lane >> 4;

    float acc[2][4][4];
#pragma unroll
    for (int mt = 0; mt < 2; ++mt)
#pragma unroll
        for (int nt = 0; nt < 4; ++nt)
#pragma unroll
            for (int r = 0; r < 4; ++r) acc[mt][nt][r] = 0.f;

    const __half* Ab = A + (size_t)rowBase * DD;
    const __half* Wb = W + (size_t)colBase * DD;

    // loader: A = 1024 chunks (4/thread), B = 512 chunks (2/thread)
#define G_ISSUE(t, s)                                                         \
    do {                                                                      \
        const unsigned sb = aSm + (s) * STGG;                                 \
        _Pragma("unroll")                                                     \
        for (int i = 0; i < 4; ++i) {                                         \
            const int id = tid + 256*i;                                       \
            const int r = id >> 3, c = id & 7;                                \
            CP_ASYNC16(sb + swz128(r, c),                                     \
                       Ab + (size_t)r * DD + (t)*BKG + c*8);                  \
        }                                                                     \
        _Pragma("unroll")                                                     \
        for (int i = 0; i < 2; ++i) {                                         \
            const int id = tid + 256*i;                                       \
            const int r = id >> 3, c = id & 7;                                \
            CP_ASYNC16(sb + OPA + swz128(r, c),                               \
                       Wb + (size_t)r * DD + (t)*BKG + c*8);                  \
        }                                                                     \
        CP_COMMIT();                                                          \
    } while (0)

    G_ISSUE(0, 0);
    G_ISSUE(1, 1);

    int buf = 0;
    for (int t = 0; t < NKTG; ++t) {
        if (t + 1 < NKTG) { CP_WAIT1(); } else { CP_WAIT0(); }
        __syncthreads();
        if (t + 2 < NKTG) G_ISSUE(t + 2, (t + 2) % 3);

        const unsigned ab = aSm + buf * STGG;
        const unsigned bb = ab + OPA;
#pragma unroll
        for (int kc = 0; kc < 4; ++kc) {
            const int ch = kc * 2 + lmSel;
            unsigned a[2][4];
#pragma unroll
            for (int mt = 0; mt < 2; ++mt)
                LDSM_X4(a[mt][0], a[mt][1], a[mt][2], a[mt][3],
                        ab + swz128(warpM + mt*16 + lmRow, ch));
            unsigned bl[4], bh[4];
#pragma unroll
            for (int nc = 0; nc < 2; ++nc) {
                unsigned x0, x1, x2, x3;
                LDSM_X4(x0, x1, x2, x3, bb + swz128(warpN + nc*16 + lmRow, ch));
                bl[2*nc] = x0; bl[2*nc+1] = x1;
                bh[2*nc] = x2; bh[2*nc+1] = x3;
            }
#pragma unroll
            for (int mt = 0; mt < 2; ++mt)
#pragma unroll
                for (int nt = 0; nt < 4; ++nt)
                    MMA_F16(acc[mt][nt][0], acc[mt][nt][1],
                            acc[mt][nt][2], acc[mt][nt][3],
                            a[mt][0], a[mt][1], a[mt][2], a[mt][3],
                            bl[nt], bh[nt]);
        }
        buf = (buf + 1) % 3;
    }
#undef G_ISSUE

#pragma unroll
    for (int mt = 0; mt < 2; ++mt) {
#pragma unroll
        for (int nt = 0; nt < 4; ++nt) {
            const int rr = rowBase + warpM + mt*16 + grp;
            const int c  = colBase + warpN + nt*8 + 2*qk;
            float2 v0 = make_float2(acc[mt][nt][0], acc[mt][nt][1]);
            float2 v1 = make_float2(acc[mt][nt][2], acc[mt][nt][3]);
            if (MODE == 0) {
                *(float2*)&Cf[(size_t)rr * DD + c]       = v0;
                *(float2*)&Cf[(size_t)(rr+8) * DD + c]   = v1;
            } else {
                const int hh = c / DH, d = c % DH;
                const int b0 = rr / TT, t0 = rr % TT;
                const int b1 = (rr+8) / TT, t1 = (rr+8) % TT;
                if (doRope) {
                    const int pair = d >> 1;
                    const float freq = powf(10000.0f, -(float)pair * (1.0f/32.0f));
                    float s0, cc0, s1, cc1;
                    sincosf((float)t0 * freq, &s0, &cc0);
                    sincosf((float)t1 * freq, &s1, &cc1);
                    v0 = make_float2(cc0*v0.x - s0*v0.y, s0*v0.x + cc0*v0.y);
                    v1 = make_float2(cc1*v1.x - s1*v1.y, s1*v1.x + cc1*v1.y);
                }
                *(unsigned*)&Ch[(((size_t)(b0*NH + hh))*TT + t0)*DH + d] =
                    pack_h2(v0.x, v0.y);
                *(unsigned*)&Ch[(((size_t)(b1*NH + hh))*TT + t1)*DH + d] =
                    pack_h2(v1.x, v1.y);
            }
        }
    }
}

__global__ __launch_bounds__(256, 3)
void hgemm16_qkv()
{
    const int z = blockIdx.z;
    __half* C = (z == 0) ? g_Qh : (z == 1) ? g_Kh : g_Vh;
    hgemm16_body<1>(g_h16, g_w16[z], nullptr, C,
                    blockIdx.y * 128, blockIdx.x * 64, z < 2);
}

__global__ __launch_bounds__(256, 3)
void hgemm16_out(float* __restrict__ out)
{
    hgemm16_body<0>(g_A16, g_w16[3], out, nullptr,
                    blockIdx.y * 128, blockIdx.x * 64, 0);
}

// ---------------------------------------------------------------------------
// fp16 flash attention (R10 winner, unchanged): log2-domain ex2 softmax,
// ones-column row-sum MMA, cp.async double-buffered K/V.
// ---------------------------------------------------------------------------
#define FKST  72
#define FTILE (64*FKST*2)

__global__ __launch_bounds__(256, 2)
void flash16()
{
    __shared__ __half sK[2*64*FKST];
    __shared__ __half sV[2*64*FKST];
    const unsigned kSm = smem_u32(sK);
    const unsigned vSm = smem_u32(sV);

    const int tid  = threadIdx.x;
    const int lane = tid & 31;
    const int warp = tid >> 5;
    const int grp  = lane >> 2;
    const int qk   = lane & 3;
    const int qtile = gridDim.x - 1 - blockIdx.x;
    const int bh    = blockIdx.y;
    const int qbase = qtile * 128;

    const __half* Qp = g_Qh + (size_t)bh * TT * DH;
    const __half* Kp = g_Kh + (size_t)bh * TT * DH;
    const __half* Vp = g_Vh + (size_t)bh * TT * DH;

    const int lmRow = lane & 15;
    const int lmSel = lane >> 4;

    const int qi0 = qbase + warp*16 + grp;
    const int qi1 = qi0 + 8;
    unsigned qa[4][4];
    {
        const __half* q0 = Qp + (size_t)qi0 * DH;
        const __half* q1 = Qp + (size_t)qi1 * DH;
#pragma unroll
        for (int kc = 0; kc < 4; ++kc) {
            qa[kc][0] = *(const unsigned*)(q0 + kc*16 + 2*qk);
            qa[kc][1] = *(const unsigned*)(q1 + kc*16 + 2*qk);
            qa[kc][2] = *(const unsigned*)(q0 + kc*16 + 8 + 2*qk);
            qa[kc][3] = *(const unsigned*)(q1 + kc*16 + 8 + 2*qk);
        }
    }

    float m0 = -1e30f, m1 = -1e30f;
    float oa[8][4];
    float oaS[4] = {0.f, 0.f, 0.f, 0.f};
#pragma unroll
    for (int nt = 0; nt < 8; ++nt)
#pragma unroll
        for (int r = 0; r < 4; ++r) oa[nt][r] = 0.f;

    if (tid < 128) {
        const int rr = tid & 63, ss = tid >> 6;
        *(uint4*)&sV[ss*64*FKST + rr*FKST + 64] = make_uint4(0x00003C00u, 0u, 0u, 0u);
    }

    const int fr = tid >> 3;
    const int fc = tid & 7;
    const unsigned dk0 = (fr*FKST + fc*8) * 2;
    const unsigned dk1 = ((fr+32)*FKST + fc*8) * 2;

#define F_ISSUE(kt, s)                                                        \
    do {                                                                      \
        const __half* ks_ = Kp + (size_t)((kt)*64 + fr) * DH + fc*8;          \
        const __half* vs_ = Vp + (size_t)((kt)*64 + fr) * DH + fc*8;          \
        CP_ASYNC16(kSm + (s)*FTILE + dk0, ks_);                               \
        CP_ASYNC16(kSm + (s)*FTILE + dk1, ks_ + (size_t)32*DH);               \
        CP_ASYNC16(vSm + (s)*FTILE + dk0, vs_);                               \
        CP_ASYNC16(vSm + (s)*FTILE + dk1, vs_ + (size_t)32*DH);               \
        CP_COMMIT();                                                          \
    } while (0)

    F_ISSUE(0, 0);

    const int lastKt = 2*qtile + 1;
    for (int kt = 0; kt <= lastKt; ++kt) {
        const int kbase = kt * 64;
        const int s = kt & 1;
        CP_WAIT0();
        __syncthreads();
        if (kt < lastKt) F_ISSUE(kt + 1, (kt + 1) & 1);

        float sa[8][4];
#pragma unroll
        for (int nt = 0; nt < 8; ++nt)
#pragma unroll
            for (int r = 0; r < 4; ++r) sa[nt][r] = 0.f;

#pragma unroll
        for (int kc = 0; kc < 4; ++kc) {
#pragma unroll
            for (int nc = 0; nc < 4; ++nc) {
                unsigned x0, x1, x2, x3;
                const unsigned addr = kSm + s*FTILE +
                    ((nc*16 + lmRow)*FKST + (kc*2 + lmSel)*8) * 2;
                LDSM_X4(x0, x1, x2, x3, addr);
                MMA_F16(sa[2*nc  ][0], sa[2*nc  ][1], sa[2*nc  ][2], sa[2*nc  ][3],
                        qa[kc][0], qa[kc][1], qa[kc][2], qa[kc][3], x0, x2);
                MMA_F16(sa[2*nc+1][0], sa[2*nc+1][1], sa[2*nc+1][2], sa[2*nc+1][3],
                        qa[kc][0], qa[kc][1], qa[kc][2], qa[kc][3], x1, x3);
            }
        }

        const float sc2 = 0.125f * 1.44269504f;
        if (kbase + 63 > qbase) {
#pragma unroll
            for (int nt = 0; nt < 8; ++nt) {
                const int c0 = kbase + nt*8 + 2*qk;
                const int c1 = c0 + 1;
                sa[nt][0] = (c0 <= qi0) ? sa[nt][0]*sc2 : -1e30f;
                sa[nt][1] = (c1 <= qi0) ? sa[nt][1]*sc2 : -1e30f;
                sa[nt][2] = (c0 <= qi1) ? sa[nt][2]*sc2 : -1e30f;
                sa[nt][3] = (c1 <= qi1) ? sa[nt][3]*sc2 : -1e30f;
            }
        } else {
#pragma unroll
            for (int nt = 0; nt < 8; ++nt)
#pragma unroll
                for (int r = 0; r < 4; ++r) sa[nt][r] *= sc2;
        }

        float mx0 = sa[0][0], mx1 = sa[0][2];
#pragma unroll
        for (int nt = 0; nt < 8; ++nt) {
            mx0 = fmaxf(mx0, fmaxf(sa[nt][0], sa[nt][1]));
            mx1 = fmaxf(mx1, fmaxf(sa[nt][2], sa[nt][3]));
        }
        mx0 = fmaxf(mx0, __shfl_xor_sync(0xffffffffu, mx0, 1));
        mx0 = fmaxf(mx0, __shfl_xor_sync(0xffffffffu, mx0, 2));
        mx1 = fmaxf(mx1, __shfl_xor_sync(0xffffffffu, mx1, 1));
        mx1 = fmaxf(mx1, __shfl_xor_sync(0xffffffffu, mx1, 2));

        const float nm0 = fmaxf(m0, mx0);
        const float nm1 = fmaxf(m1, mx1);
        const float al0 = fex2(m0 - nm0);
        const float al1 = fex2(m1 - nm1);
        m0 = nm0; m1 = nm1;

#pragma unroll
        for (int nt = 0; nt < 8; ++nt) {
            oa[nt][0] *= al0; oa[nt][1] *= al0;
            oa[nt][2] *= al1; oa[nt][3] *= al1;
        }
        oaS[0] *= al0; oaS[1] *= al0;
        oaS[2] *= al1; oaS[3] *= al1;

#pragma unroll
        for (int kc = 0; kc < 4; ++kc) {
            unsigned a0 = pack_h2(sa[2*kc  ][0] - nm0, sa[2*kc  ][1] - nm0);
            unsigned a1 = pack_h2(sa[2*kc  ][2] - nm1, sa[2*kc  ][3] - nm1);
            unsigned a2 = pack_h2(sa[2*kc+1][0] - nm0, sa[2*kc+1][1] - nm0);
            unsigned a3 = pack_h2(sa[2*kc+1][2] - nm1, sa[2*kc+1][3] - nm1);
            H2EX2(a0, a0); H2EX2(a1, a1); H2EX2(a2, a2); H2EX2(a3, a3);

            const unsigned raddr = vSm + s*FTILE +
                (((kc*16 + lmRow) * FKST) + lmSel*8) * 2;
#pragma unroll
            for (int np = 0; np < 4; ++np) {
                unsigned b0, b1, b2, b3;
                LDSM_X4_TRANS(b0, b1, b2, b3, raddr + np*32);
                MMA_F16(oa[2*np  ][0], oa[2*np  ][1], oa[2*np  ][2], oa[2*np  ][3],
                        a0, a1, a2, a3, b0, b1);
                MMA_F16(oa[2*np+1][0], oa[2*np+1][1], oa[2*np+1][2], oa[2*np+1][3],
                        a0, a1, a2, a3, b2, b3);
            }
            unsigned s0, s1;
            LDSM_X2_TRANS(s0, s1, vSm + s*FTILE + ((kc*16 + lmRow)*FKST + 64)*2);
            MMA_F16(oaS[0], oaS[1], oaS[2], oaS[3], a0, a1, a2, a3, s0, s1);
        }
    }
#undef F_ISSUE

    const float l0 = __shfl_sync(0xffffffffu, oaS[0], lane & ~3);
    const float l1 = __shfl_sync(0xffffffffu, oaS[2], lane & ~3);
    const int b = bh / NH, hh = bh % NH;
    const float inv0 = 1.f / l0;
    const float inv1 = 1.f / l1;
    __half* d0 = g_A16 + ((size_t)(b*TT + qi0))*DD + hh*DH;
    __half* d1 = g_A16 + ((size_t)(b*TT + qi1))*DD + hh*DH;
#pragma unroll
    for (int nt = 0; nt < 8; ++nt) {
        const int c = nt*8 + 2*qk;
        *(unsigned*)&d0[c] = pack_h2(oa[nt][0]*inv0, oa[nt][1]*inv0);
        *(unsigned*)&d1[c] = pack_h2(oa[nt][2]*inv1, oa[nt][3]*inv1);
    }
}

// ---------------------------------------------------------------------------
extern "C" void kernel_launch(void* const* d_in, const int* in_sizes, int n_in,
                              void* d_out, int out_size)
{
    const float* h  = (const float*)d_in[0];
    const float* wq = (const float*)d_in[1];
    const float* wk = (const float*)d_in[2];
    const float* wv = (const float*)d_in[3];
    const float* wo = (const float*)d_in[4];
    float* out = (float*)d_out;
    (void)in_sizes; (void)n_in; (void)out_size;

    cudaFuncSetAttribute(hgemm16_qkv, cudaFuncAttributeMaxDynamicSharedMemorySize, GSMEM);
    cudaFuncSetAttribute(hgemm16_out, cudaFuncAttributeMaxDynamicSharedMemorySize, GSMEM);

    cvt5<<<dim3(BT*DD/(256*8), 5), 256>>>(h, wq, wk, wv, wo);

    hgemm16_qkv<<<dim3(DD/64, BT/128, 3), 256, GSMEM>>>();

    flash16<<<dim3(TT/128, BB*NH), 256>>>();

    hgemm16_out<<<dim3(DD/64, BT/128), 256, GSMEM>>>(out);
}